// round 1
// baseline (speedup 1.0000x reference)
#include <cuda_runtime.h>
#include <math.h>
#include <stdint.h>

// Problem constants
#define Bc  2
#define Sc  2048
#define Hc  4096
#define NHc 32
#define HDc 128
// 1/sqrt(128)
#define INV_NORM 0.08838834764831845f

// ---------------------------------------------------------------------------
// Device scratch (allocation-free rule: __device__ globals)
// ---------------------------------------------------------------------------
__device__ float g_q[(size_t)Bc * NHc * Sc * HDc];   // [B,NH,S,HD]
__device__ float g_k[(size_t)Bc * NHc * Sc * HDc];
__device__ float g_v[(size_t)Bc * NHc * Sc * HDc];
__device__ float g_ctx[(size_t)Bc * Sc * Hc];        // [B,S,H]

// ---------------------------------------------------------------------------
// Kernel 1: fused QKV projection.
//   C[m,n] = sum_k hidden[m,k] * W_qkv[n,k] + b_qkv[n]
//   m = b*S+s in [0,4096), n in [0,12288). n -> (nh, which, hd).
//   Since BN=128 and 3*HD=384=3*128, each N-block maps to exactly one of
//   q/k/v with a fixed head: free transposed store into [B,NH,S,HD].
// ---------------------------------------------------------------------------
__global__ __launch_bounds__(256) void qkv_gemm(
    const float* __restrict__ A,      // [4096, 4096]
    const float* __restrict__ W,      // [12288, 4096]
    const float* __restrict__ bias)   // [12288]
{
    __shared__ float As[16][132];
    __shared__ float Ws[16][132];

    const int t  = threadIdx.x;
    const int bm = blockIdx.y * 128;
    const int bn = blockIdx.x * 128;
    const int tx = t & 15;
    const int ty = t >> 4;

    float acc[8][8];
#pragma unroll
    for (int i = 0; i < 8; i++)
#pragma unroll
        for (int j = 0; j < 8; j++) acc[i][j] = 0.f;

    const int lrow = t >> 2;          // 0..63 (rows lrow and lrow+64)
    const int lc4  = (t & 3) * 4;     // 0,4,8,12

    for (int k0 = 0; k0 < 4096; k0 += 16) {
#pragma unroll
        for (int u = 0; u < 2; u++) {
            int row = lrow + u * 64;
            float4 av = *(const float4*)(A + (size_t)(bm + row) * 4096 + k0 + lc4);
            As[lc4 + 0][row] = av.x; As[lc4 + 1][row] = av.y;
            As[lc4 + 2][row] = av.z; As[lc4 + 3][row] = av.w;
            float4 wv = *(const float4*)(W + (size_t)(bn + row) * 4096 + k0 + lc4);
            Ws[lc4 + 0][row] = wv.x; Ws[lc4 + 1][row] = wv.y;
            Ws[lc4 + 2][row] = wv.z; Ws[lc4 + 3][row] = wv.w;
        }
        __syncthreads();
#pragma unroll
        for (int kk = 0; kk < 16; kk++) {
            float a[8], b[8];
            *(float4*)&a[0] = *(const float4*)&As[kk][ty * 4];
            *(float4*)&a[4] = *(const float4*)&As[kk][64 + ty * 4];
            *(float4*)&b[0] = *(const float4*)&Ws[kk][tx * 4];
            *(float4*)&b[4] = *(const float4*)&Ws[kk][64 + tx * 4];
#pragma unroll
            for (int i = 0; i < 8; i++)
#pragma unroll
                for (int j = 0; j < 8; j++) acc[i][j] += a[i] * b[j];
        }
        __syncthreads();
    }

    // Epilogue: route this 128-wide N block to q/k/v.
    const int nh    = bn / 384;
    const int which = (bn % 384) >> 7;
    float* dst = (which == 0) ? g_q : ((which == 1) ? g_k : g_v);

#pragma unroll
    for (int i = 0; i < 8; i++) {
        int m  = bm + ((i < 4) ? (ty * 4 + i) : (64 + ty * 4 + (i - 4)));
        int bb = m >> 11;          // / S
        int s  = m & 2047;         // % S
        float* drow = dst + (((size_t)bb * NHc + nh) * Sc + s) * HDc;
#pragma unroll
        for (int j = 0; j < 8; j++) {
            int n = (j < 4) ? (tx * 4 + j) : (64 + tx * 4 + (j - 4));  // hd
            drow[n] = acc[i][j] + bias[bn + n];
        }
    }
}

// ---------------------------------------------------------------------------
// Kernel 2: flash attention with ALiBi + causal mask.
//   grid = (S/64, B*NH), block = 256.
//   Thread t: row r = t/4 of the 64-query tile, quad lane q4 = t&3.
//   Scores: 16 cols per thread (c = q4 + 4*jj), O: 32 cols (c = g*32+q4*8+j).
// ---------------------------------------------------------------------------
__global__ __launch_bounds__(256) void attn_kernel(const float* __restrict__ alibi)
{
    extern __shared__ float sm[];
    float* Qs = sm;                    // [64][132]
    float* Ks = sm + 64 * 132;         // [64][132]
    float* Vs = sm + 2 * 64 * 132;     // [64][132]
    float* Ps = sm + 3 * 64 * 132;     // [64][68]

    const int t  = threadIdx.x;
    const int qt = blockIdx.x;         // q tile index
    const int bh = blockIdx.y;         // b*NH + nh
    const int q0 = qt * 64;

    const float* qg = g_q + ((size_t)bh * Sc + q0) * HDc;
    const float* kgb = g_k + (size_t)bh * Sc * HDc;
    const float* vgb = g_v + (size_t)bh * Sc * HDc;
    const float* al  = alibi + (size_t)bh * Sc;

    // Load + scale Q tile (64x128) cooperatively: 2048 float4 / 256 thr = 8.
#pragma unroll
    for (int u = 0; u < 8; u++) {
        int id  = u * 256 + t;
        int row = id >> 5;
        int c4  = (id & 31) * 4;
        float4 v = *(const float4*)(qg + (size_t)row * HDc + c4);
        v.x *= INV_NORM; v.y *= INV_NORM; v.z *= INV_NORM; v.w *= INV_NORM;
        *(float4*)&Qs[row * 132 + c4] = v;
    }

    const int r  = t >> 2;
    const int q4 = t & 3;
    float m_r = -INFINITY;
    float l_r = 0.f;
    float o[4][8];
#pragma unroll
    for (int g = 0; g < 4; g++)
#pragma unroll
        for (int j = 0; j < 8; j++) o[g][j] = 0.f;

    for (int j = 0; j <= qt; j++) {
        __syncthreads();   // Qs ready (iter 0) / previous tile fully consumed
        const float* kg = kgb + (size_t)j * 64 * HDc;
        const float* vg = vgb + (size_t)j * 64 * HDc;
#pragma unroll
        for (int u = 0; u < 8; u++) {
            int id  = u * 256 + t;
            int row = id >> 5;
            int c4  = (id & 31) * 4;
            *(float4*)&Ks[row * 132 + c4] = *(const float4*)(kg + (size_t)row * HDc + c4);
            *(float4*)&Vs[row * 132 + c4] = *(const float4*)(vg + (size_t)row * HDc + c4);
        }
        __syncthreads();

        // ---- scores: sc[jj] = q_row . k_col, col = q4 + 4*jj ----
        float sc[16];
#pragma unroll
        for (int jj = 0; jj < 16; jj++) sc[jj] = 0.f;
#pragma unroll 4
        for (int d4 = 0; d4 < 32; d4++) {
            float4 qv = *(const float4*)&Qs[r * 132 + d4 * 4];
#pragma unroll
            for (int jj = 0; jj < 16; jj++) {
                float4 kv = *(const float4*)&Ks[(q4 + 4 * jj) * 132 + d4 * 4];
                sc[jj] += qv.x * kv.x + qv.y * kv.y + qv.z * kv.z + qv.w * kv.w;
            }
        }

        // ---- alibi + causal ----
        const int kbase = j * 64 + q4;
        const int qglob = q0 + r;
#pragma unroll
        for (int jj = 0; jj < 16; jj++) {
            int kglob = kbase + 4 * jj;
            sc[jj] += __ldg(&al[kglob]);
            if (j == qt && kglob > qglob) sc[jj] = -1e30f;
        }

        // ---- online softmax over the quad (lanes 4r..4r+3) ----
        float mx = sc[0];
#pragma unroll
        for (int jj = 1; jj < 16; jj++) mx = fmaxf(mx, sc[jj]);
        mx = fmaxf(mx, __shfl_xor_sync(0xffffffffu, mx, 1));
        mx = fmaxf(mx, __shfl_xor_sync(0xffffffffu, mx, 2));
        float m_new = fmaxf(m_r, mx);
        float corr  = __expf(m_r - m_new);
        float psum  = 0.f;
#pragma unroll
        for (int jj = 0; jj < 16; jj++) {
            float p = __expf(sc[jj] - m_new);
            psum += p;
            Ps[r * 68 + q4 + 4 * jj] = p;
        }
        psum += __shfl_xor_sync(0xffffffffu, psum, 1);
        psum += __shfl_xor_sync(0xffffffffu, psum, 2);
        l_r = l_r * corr + psum;
        m_r = m_new;
#pragma unroll
        for (int g = 0; g < 4; g++)
#pragma unroll
            for (int jj = 0; jj < 8; jj++) o[g][jj] *= corr;
        __syncwarp();  // Ps row written by this quad, read by this quad

        // ---- O += P @ V ----
#pragma unroll 4
        for (int kk = 0; kk < 64; kk++) {
            float p = Ps[r * 68 + kk];
#pragma unroll
            for (int g = 0; g < 4; g++) {
                float4 v0 = *(const float4*)&Vs[kk * 132 + g * 32 + q4 * 8];
                float4 v1 = *(const float4*)&Vs[kk * 132 + g * 32 + q4 * 8 + 4];
                o[g][0] += p * v0.x; o[g][1] += p * v0.y;
                o[g][2] += p * v0.z; o[g][3] += p * v0.w;
                o[g][4] += p * v1.x; o[g][5] += p * v1.y;
                o[g][6] += p * v1.z; o[g][7] += p * v1.w;
            }
        }
    }

    // ---- normalize + write ctx in [B,S,H] (h = nh*128 + c) ----
    const float inv_l = 1.f / l_r;
    const int b  = bh >> 5;
    const int nh = bh & 31;
    float* crow = g_ctx + ((size_t)(b * Sc + q0 + r)) * Hc + nh * HDc;
#pragma unroll
    for (int g = 0; g < 4; g++) {
        float4 s0, s1;
        s0.x = o[g][0] * inv_l; s0.y = o[g][1] * inv_l;
        s0.z = o[g][2] * inv_l; s0.w = o[g][3] * inv_l;
        s1.x = o[g][4] * inv_l; s1.y = o[g][5] * inv_l;
        s1.z = o[g][6] * inv_l; s1.w = o[g][7] * inv_l;
        *(float4*)&crow[g * 32 + q4 * 8]     = s0;
        *(float4*)&crow[g * 32 + q4 * 8 + 4] = s1;
    }
}

// ---------------------------------------------------------------------------
// Kernel 3: dense projection + bias + residual.
//   out[m,n] = sum_k ctx[m,k] * W_dense[n,k] + b_dense[n] + residual[m,n]
// ---------------------------------------------------------------------------
__global__ __launch_bounds__(256) void dense_gemm(
    const float* __restrict__ W,        // [4096, 4096]
    const float* __restrict__ bias,     // [4096]
    const float* __restrict__ residual, // [4096, 4096]
    float* __restrict__ out)            // [4096, 4096]
{
    __shared__ float As[16][132];
    __shared__ float Ws[16][132];

    const int t  = threadIdx.x;
    const int bm = blockIdx.y * 128;
    const int bn = blockIdx.x * 128;
    const int tx = t & 15;
    const int ty = t >> 4;
    const float* A = g_ctx;

    float acc[8][8];
#pragma unroll
    for (int i = 0; i < 8; i++)
#pragma unroll
        for (int j = 0; j < 8; j++) acc[i][j] = 0.f;

    const int lrow = t >> 2;
    const int lc4  = (t & 3) * 4;

    for (int k0 = 0; k0 < 4096; k0 += 16) {
#pragma unroll
        for (int u = 0; u < 2; u++) {
            int row = lrow + u * 64;
            float4 av = *(const float4*)(A + (size_t)(bm + row) * 4096 + k0 + lc4);
            As[lc4 + 0][row] = av.x; As[lc4 + 1][row] = av.y;
            As[lc4 + 2][row] = av.z; As[lc4 + 3][row] = av.w;
            float4 wv = *(const float4*)(W + (size_t)(bn + row) * 4096 + k0 + lc4);
            Ws[lc4 + 0][row] = wv.x; Ws[lc4 + 1][row] = wv.y;
            Ws[lc4 + 2][row] = wv.z; Ws[lc4 + 3][row] = wv.w;
        }
        __syncthreads();
#pragma unroll
        for (int kk = 0; kk < 16; kk++) {
            float a[8], b[8];
            *(float4*)&a[0] = *(const float4*)&As[kk][ty * 4];
            *(float4*)&a[4] = *(const float4*)&As[kk][64 + ty * 4];
            *(float4*)&b[0] = *(const float4*)&Ws[kk][tx * 4];
            *(float4*)&b[4] = *(const float4*)&Ws[kk][64 + tx * 4];
#pragma unroll
            for (int i = 0; i < 8; i++)
#pragma unroll
                for (int j = 0; j < 8; j++) acc[i][j] += a[i] * b[j];
        }
        __syncthreads();
    }

#pragma unroll
    for (int i = 0; i < 8; i++) {
        int m = bm + ((i < 4) ? (ty * 4 + i) : (64 + ty * 4 + (i - 4)));
#pragma unroll
        for (int j = 0; j < 8; j++) {
            int nl = (j < 4) ? (tx * 4 + j) : (64 + tx * 4 + (j - 4));
            int n  = bn + nl;
            out[(size_t)m * Hc + n] = acc[i][j] + bias[n] + residual[(size_t)m * Hc + n];
        }
    }
}

// ---------------------------------------------------------------------------
// Launch
// ---------------------------------------------------------------------------
extern "C" void kernel_launch(void* const* d_in, const int* in_sizes, int n_in,
                              void* d_out, int out_size)
{
    (void)in_sizes; (void)n_in; (void)out_size;
    const float* hidden   = (const float*)d_in[0];
    const float* residual = (const float*)d_in[1];
    const float* alibi    = (const float*)d_in[2];
    // d_in[3] = attention_mask (pure causal additive mask; applied analytically)
    const float* W_qkv    = (const float*)d_in[4];
    const float* b_qkv    = (const float*)d_in[5];
    const float* W_dense  = (const float*)d_in[6];
    const float* b_dense  = (const float*)d_in[7];
    float* out = (float*)d_out;

    // 1) fused QKV projection -> g_q / g_k / g_v
    qkv_gemm<<<dim3(96, 32), 256>>>(hidden, W_qkv, b_qkv);

    // 2) attention -> g_ctx
    const int ATTN_SMEM = (3 * 64 * 132 + 64 * 68) * (int)sizeof(float); // 118784 B
    cudaFuncSetAttribute(attn_kernel, cudaFuncAttributeMaxDynamicSharedMemorySize,
                         ATTN_SMEM);
    attn_kernel<<<dim3(Sc / 64, Bc * NHc), 256, ATTN_SMEM>>>(alibi);

    // 3) dense + bias + residual -> out
    dense_gemm<<<dim3(32, 32), 256>>>(W_dense, b_dense, residual, out);
}

// round 3
// speedup vs baseline: 1.6479x; 1.6479x over previous
#include <cuda_runtime.h>
#include <cuda_bf16.h>
#include <math.h>
#include <stdint.h>

// ---------------------------------------------------------------------------
// Problem constants
// ---------------------------------------------------------------------------
#define Bc  2
#define Sc  2048
#define Hc  4096
#define NHc 32
#define HDc 128
#define INV_NORM 0.08838834764831845f

// ---------------------------------------------------------------------------
// Device scratch (__device__ globals: allocation-free rule)
// ---------------------------------------------------------------------------
__device__ __align__(256) __nv_bfloat16 g_Ahi[(size_t)4096 * 4096];
__device__ __align__(256) __nv_bfloat16 g_Alo[(size_t)4096 * 4096];
__device__ __align__(256) __nv_bfloat16 g_Wqhi[(size_t)12288 * 4096];
__device__ __align__(256) __nv_bfloat16 g_Wqlo[(size_t)12288 * 4096];
__device__ __align__(256) __nv_bfloat16 g_Wdhi[(size_t)4096 * 4096];
__device__ __align__(256) __nv_bfloat16 g_Wdlo[(size_t)4096 * 4096];
__device__ __align__(256) __nv_bfloat16 g_Chi[(size_t)4096 * 4096];
__device__ __align__(256) __nv_bfloat16 g_Clo[(size_t)4096 * 4096];

__device__ __align__(256) float g_q[(size_t)Bc * NHc * Sc * HDc];   // [B,NH,S,HD]
__device__ __align__(256) float g_k[(size_t)Bc * NHc * Sc * HDc];
__device__ __align__(256) float g_v[(size_t)Bc * NHc * Sc * HDc];
__device__ __align__(256) float g_ctx[(size_t)Bc * Sc * Hc];        // [B,S,H]

// ---------------------------------------------------------------------------
// PTX helpers (sm_80-era only: mma.sync / ldmatrix / cp.async — the harness's
// PTX target is plain sm_103, so no tcgen05 / 'a'-suffix features anywhere)
// ---------------------------------------------------------------------------
__device__ __forceinline__ uint32_t smem_u32(const void* p) {
    uint32_t a;
    asm("{ .reg .u64 t; cvta.to.shared.u64 t, %1; cvt.u32.u64 %0, t; }"
        : "=r"(a) : "l"(p));
    return a;
}

__device__ __forceinline__ void cp16(uint32_t s, const void* g) {
    asm volatile("cp.async.cg.shared.global [%0], [%1], 16;" :: "r"(s), "l"(g));
}
#define CP_COMMIT() asm volatile("cp.async.commit_group;" ::: "memory")
#define CP_WAIT2()  asm volatile("cp.async.wait_group 2;" ::: "memory")

__device__ __forceinline__ void ldsm_x4(uint32_t* r, uint32_t a) {
    asm volatile("ldmatrix.sync.aligned.m8n8.x4.shared.b16 {%0,%1,%2,%3}, [%4];"
        : "=r"(r[0]), "=r"(r[1]), "=r"(r[2]), "=r"(r[3]) : "r"(a));
}
__device__ __forceinline__ void ldsm_x2(uint32_t* r, uint32_t a) {
    asm volatile("ldmatrix.sync.aligned.m8n8.x2.shared.b16 {%0,%1}, [%2];"
        : "=r"(r[0]), "=r"(r[1]) : "r"(a));
}
__device__ __forceinline__ void mma_bf16(float* c, const uint32_t* a, const uint32_t* b) {
    asm volatile(
        "mma.sync.aligned.m16n8k16.row.col.f32.bf16.bf16.f32 "
        "{%0,%1,%2,%3}, {%4,%5,%6,%7}, {%8,%9}, {%0,%1,%2,%3};"
        : "+f"(c[0]), "+f"(c[1]), "+f"(c[2]), "+f"(c[3])
        : "r"(a[0]), "r"(a[1]), "r"(a[2]), "r"(a[3]), "r"(b[0]), "r"(b[1]));
}

// ---------------------------------------------------------------------------
// Kernel: split fp32 -> (hi, lo) bf16 pair
// ---------------------------------------------------------------------------
__global__ __launch_bounds__(256) void split_bf16(
    const float* __restrict__ x,
    __nv_bfloat16* __restrict__ hi,
    __nv_bfloat16* __restrict__ lo,
    int n)
{
    int i = (blockIdx.x * 256 + threadIdx.x) * 4;
    if (i >= n) return;
    float4 v = *(const float4*)(x + i);
    __nv_bfloat16 h0 = __float2bfloat16(v.x);
    __nv_bfloat16 h1 = __float2bfloat16(v.y);
    __nv_bfloat16 h2 = __float2bfloat16(v.z);
    __nv_bfloat16 h3 = __float2bfloat16(v.w);
    __nv_bfloat16 l0 = __float2bfloat16(v.x - __bfloat162float(h0));
    __nv_bfloat16 l1 = __float2bfloat16(v.y - __bfloat162float(h1));
    __nv_bfloat16 l2 = __float2bfloat16(v.z - __bfloat162float(h2));
    __nv_bfloat16 l3 = __float2bfloat16(v.w - __bfloat162float(h3));
    __nv_bfloat162* hp = (__nv_bfloat162*)(hi + i);
    __nv_bfloat162* lp = (__nv_bfloat162*)(lo + i);
    hp[0] = __nv_bfloat162(h0, h1); hp[1] = __nv_bfloat162(h2, h3);
    lp[0] = __nv_bfloat162(l0, l1); lp[1] = __nv_bfloat162(l2, l3);
}

// ---------------------------------------------------------------------------
// Kernel: HMMA bf16 3-pass split GEMM.
//   C[128 x 128 tile] = A[M,K] * B[N,K]^T, fp32 register accumulators.
//   passes: Ahi*Bhi + Ahi*Blo + Alo*Bhi
//   mode 0: QKV epilogue (+bias, scatter to g_q/g_k/g_v [B,NH,S,HD])
//   mode 1: dense epilogue (+bias +residual -> out [M,H])
// ---------------------------------------------------------------------------
#define BK        32
#define ROWB      80            // padded row stride in bytes (32 bf16 = 64B + 16)
#define BUF_BYTES (128 * ROWB)  // 10240 per operand-half
#define STG_BYTES (4 * BUF_BYTES)
#define N_STAGES  3
#define GEMM_SMEM (N_STAGES * STG_BYTES)

__global__ __launch_bounds__(256, 1) void hmma_gemm(
    const __nv_bfloat16* __restrict__ Ahi, const __nv_bfloat16* __restrict__ Alo,
    const __nv_bfloat16* __restrict__ Bhi, const __nv_bfloat16* __restrict__ Blo,
    const float* __restrict__ bias, const float* __restrict__ residual,
    float* __restrict__ out, int K, int mode)
{
    extern __shared__ char smem[];
    const uint32_t sb = smem_u32(smem);
    const int t    = threadIdx.x;
    const int wid  = t >> 5;
    const int lane = t & 31;
    const int wm   = wid >> 2;       // 0..1  (M dir, 64 rows each)
    const int wn   = wid & 3;        // 0..3  (N dir, 32 cols each)
    const int bm   = blockIdx.x * 128;
    const int bn   = blockIdx.y * 128;
    const int NK   = K / BK;

    float c[4][4][4];
#pragma unroll
    for (int mi = 0; mi < 4; mi++)
#pragma unroll
        for (int ni = 0; ni < 4; ni++)
#pragma unroll
            for (int e = 0; e < 4; e++) c[mi][ni][e] = 0.f;

    const __nv_bfloat16* srcA_hi = Ahi + (size_t)bm * K;
    const __nv_bfloat16* srcA_lo = Alo + (size_t)bm * K;
    const __nv_bfloat16* srcB_hi = Bhi + (size_t)bn * K;
    const __nv_bfloat16* srcB_lo = Blo + (size_t)bn * K;

    // stage loader: 4 bufs x 128 rows x 64B (as 4x16B chunks), 8 cp per thread
    auto load_stage = [&](int st, int k0) {
        uint32_t s0 = sb + (uint32_t)st * STG_BYTES;
        const __nv_bfloat16* srcs[4] = { srcA_hi, srcA_lo, srcB_hi, srcB_lo };
#pragma unroll
        for (int bfi = 0; bfi < 4; bfi++) {
#pragma unroll
            for (int u = 0; u < 2; u++) {
                int id = u * 256 + t;          // 0..511
                int r  = id >> 2, cc = id & 3;
                cp16(s0 + (uint32_t)bfi * BUF_BYTES + (uint32_t)(r * ROWB + cc * 16),
                     srcs[bfi] + (size_t)r * K + k0 + cc * 8);
            }
        }
        CP_COMMIT();
    };

    load_stage(0, 0);
    load_stage(1, BK);

    // lane-derived ldmatrix address components
    const int a_row = (lane & 15);            // rows of the 16x16 A frag
    const int a_coff = (lane >> 4) * 16;      // +16B for k 8..15 halves
    const int b_row = (lane & 7);             // rows (n) of the 16x8 B frag
    const int b_coff = ((lane >> 3) & 1) * 16;

    int st = 0;
    for (int i = 0; i < NK; ++i) {
        if (i + 2 < NK) load_stage((i + 2) % N_STAGES, (i + 2) * BK);
        else            CP_COMMIT();          // keep group accounting uniform
        CP_WAIT2();
        __syncthreads();

        const uint32_t sa = sb + (uint32_t)st * STG_BYTES + (uint32_t)(wm * 64) * ROWB;
        const uint32_t sB = sb + (uint32_t)st * STG_BYTES + 2u * BUF_BYTES
                          + (uint32_t)(wn * 32) * ROWB;
#pragma unroll
        for (int kb = 0; kb < 2; ++kb) {
            const int kcol = kb * 32;
            uint32_t bh[4][2], bl[4][2];
#pragma unroll
            for (int ni = 0; ni < 4; ++ni) {
                uint32_t addr = sB + (uint32_t)((ni * 8 + b_row) * ROWB + kcol + b_coff);
                ldsm_x2(bh[ni], addr);
                ldsm_x2(bl[ni], addr + BUF_BYTES);
            }
#pragma unroll
            for (int mi = 0; mi < 4; ++mi) {
                uint32_t ah[4], al[4];
                uint32_t addr = sa + (uint32_t)((mi * 16 + a_row) * ROWB + kcol + a_coff);
                ldsm_x4(ah, addr);
                ldsm_x4(al, addr + BUF_BYTES);
#pragma unroll
                for (int ni = 0; ni < 4; ++ni) {
                    mma_bf16(c[mi][ni], ah, bh[ni]);
                    mma_bf16(c[mi][ni], ah, bl[ni]);
                    mma_bf16(c[mi][ni], al, bh[ni]);
                }
            }
        }
        __syncthreads();
        st = (st + 1 == N_STAGES) ? 0 : st + 1;
    }

    // ---- epilogue: direct register -> gmem (quad writes 32B sectors) ----
    const int qr = lane >> 2;
    const int qc = (lane & 3) * 2;

    if (mode == 0) {
        const int nh    = bn / 384;
        const int which = (bn % 384) >> 7;
        float* dst = (which == 0) ? g_q : ((which == 1) ? g_k : g_v);
#pragma unroll
        for (int mi = 0; mi < 4; ++mi) {
#pragma unroll
            for (int rr = 0; rr < 2; ++rr) {
                int m = bm + wm * 64 + mi * 16 + qr + rr * 8;
                int b = m >> 11, s = m & 2047;
                float* drow = dst + (((size_t)b * NHc + nh) * Sc + s) * HDc;
#pragma unroll
                for (int ni = 0; ni < 4; ++ni) {
                    int hd = wn * 32 + ni * 8 + qc;
                    int n  = bn + hd - (bn & 127) + hd;  // see below
                    (void)n;
                    float2 v;
                    v.x = c[mi][ni][rr * 2 + 0] + __ldg(&bias[bn + hd]);
                    v.y = c[mi][ni][rr * 2 + 1] + __ldg(&bias[bn + hd + 1]);
                    *(float2*)(drow + hd) = v;
                }
            }
        }
    } else {
#pragma unroll
        for (int mi = 0; mi < 4; ++mi) {
#pragma unroll
            for (int rr = 0; rr < 2; ++rr) {
                int m = bm + wm * 64 + mi * 16 + qr + rr * 8;
#pragma unroll
                for (int ni = 0; ni < 4; ++ni) {
                    int n = bn + wn * 32 + ni * 8 + qc;
                    size_t o = (size_t)m * Hc + n;
                    float2 rv = *(const float2*)(residual + o);
                    float2 v;
                    v.x = c[mi][ni][rr * 2 + 0] + __ldg(&bias[n])     + rv.x;
                    v.y = c[mi][ni][rr * 2 + 1] + __ldg(&bias[n + 1]) + rv.y;
                    *(float2*)(out + o) = v;
                }
            }
        }
    }
}

// ---------------------------------------------------------------------------
// Kernel: flash attention with ALiBi + causal mask (fp32, from round 1)
// ---------------------------------------------------------------------------
__global__ __launch_bounds__(256) void attn_kernel(const float* __restrict__ alibi)
{
    extern __shared__ float sm[];
    float* Qs = sm;                    // [64][132]
    float* Ks = sm + 64 * 132;
    float* Vs = sm + 2 * 64 * 132;
    float* Ps = sm + 3 * 64 * 132;     // [64][68]

    const int t  = threadIdx.x;
    const int qt = blockIdx.x;
    const int bh = blockIdx.y;
    const int q0 = qt * 64;

    const float* qg  = g_q + ((size_t)bh * Sc + q0) * HDc;
    const float* kgb = g_k + (size_t)bh * Sc * HDc;
    const float* vgb = g_v + (size_t)bh * Sc * HDc;
    const float* al  = alibi + (size_t)bh * Sc;

#pragma unroll
    for (int u = 0; u < 8; u++) {
        int id  = u * 256 + t;
        int row = id >> 5;
        int c4  = (id & 31) * 4;
        float4 v = *(const float4*)(qg + (size_t)row * HDc + c4);
        v.x *= INV_NORM; v.y *= INV_NORM; v.z *= INV_NORM; v.w *= INV_NORM;
        *(float4*)&Qs[row * 132 + c4] = v;
    }

    const int r  = t >> 2;
    const int q4 = t & 3;
    float m_r = -INFINITY;
    float l_r = 0.f;
    float o[4][8];
#pragma unroll
    for (int g = 0; g < 4; g++)
#pragma unroll
        for (int j = 0; j < 8; j++) o[g][j] = 0.f;

    for (int j = 0; j <= qt; j++) {
        __syncthreads();
        const float* kg = kgb + (size_t)j * 64 * HDc;
        const float* vg = vgb + (size_t)j * 64 * HDc;
#pragma unroll
        for (int u = 0; u < 8; u++) {
            int id  = u * 256 + t;
            int row = id >> 5;
            int c4  = (id & 31) * 4;
            *(float4*)&Ks[row * 132 + c4] = *(const float4*)(kg + (size_t)row * HDc + c4);
            *(float4*)&Vs[row * 132 + c4] = *(const float4*)(vg + (size_t)row * HDc + c4);
        }
        __syncthreads();

        float sc[16];
#pragma unroll
        for (int jj = 0; jj < 16; jj++) sc[jj] = 0.f;
#pragma unroll 4
        for (int d4 = 0; d4 < 32; d4++) {
            float4 qv = *(const float4*)&Qs[r * 132 + d4 * 4];
#pragma unroll
            for (int jj = 0; jj < 16; jj++) {
                float4 kv = *(const float4*)&Ks[(q4 + 4 * jj) * 132 + d4 * 4];
                sc[jj] += qv.x * kv.x + qv.y * kv.y + qv.z * kv.z + qv.w * kv.w;
            }
        }

        const int kbase = j * 64 + q4;
        const int qglob = q0 + r;
#pragma unroll
        for (int jj = 0; jj < 16; jj++) {
            int kglob = kbase + 4 * jj;
            sc[jj] += __ldg(&al[kglob]);
            if (j == qt && kglob > qglob) sc[jj] = -1e30f;
        }

        float mx = sc[0];
#pragma unroll
        for (int jj = 1; jj < 16; jj++) mx = fmaxf(mx, sc[jj]);
        mx = fmaxf(mx, __shfl_xor_sync(0xffffffffu, mx, 1));
        mx = fmaxf(mx, __shfl_xor_sync(0xffffffffu, mx, 2));
        float m_new = fmaxf(m_r, mx);
        float corr  = __expf(m_r - m_new);
        float psum  = 0.f;
#pragma unroll
        for (int jj = 0; jj < 16; jj++) {
            float p = __expf(sc[jj] - m_new);
            psum += p;
            Ps[r * 68 + q4 + 4 * jj] = p;
        }
        psum += __shfl_xor_sync(0xffffffffu, psum, 1);
        psum += __shfl_xor_sync(0xffffffffu, psum, 2);
        l_r = l_r * corr + psum;
        m_r = m_new;
#pragma unroll
        for (int g = 0; g < 4; g++)
#pragma unroll
            for (int jj = 0; jj < 8; jj++) o[g][jj] *= corr;
        __syncwarp();

#pragma unroll 4
        for (int kk = 0; kk < 64; kk++) {
            float p = Ps[r * 68 + kk];
#pragma unroll
            for (int g = 0; g < 4; g++) {
                float4 v0 = *(const float4*)&Vs[kk * 132 + g * 32 + q4 * 8];
                float4 v1 = *(const float4*)&Vs[kk * 132 + g * 32 + q4 * 8 + 4];
                o[g][0] += p * v0.x; o[g][1] += p * v0.y;
                o[g][2] += p * v0.z; o[g][3] += p * v0.w;
                o[g][4] += p * v1.x; o[g][5] += p * v1.y;
                o[g][6] += p * v1.z; o[g][7] += p * v1.w;
            }
        }
    }

    const float inv_l = 1.f / l_r;
    const int b  = bh >> 5;
    const int nh = bh & 31;
    float* crow = g_ctx + ((size_t)(b * Sc + q0 + r)) * Hc + nh * HDc;
#pragma unroll
    for (int g = 0; g < 4; g++) {
        float4 s0, s1;
        s0.x = o[g][0] * inv_l; s0.y = o[g][1] * inv_l;
        s0.z = o[g][2] * inv_l; s0.w = o[g][3] * inv_l;
        s1.x = o[g][4] * inv_l; s1.y = o[g][5] * inv_l;
        s1.z = o[g][6] * inv_l; s1.w = o[g][7] * inv_l;
        *(float4*)&crow[g * 32 + q4 * 8]     = s0;
        *(float4*)&crow[g * 32 + q4 * 8 + 4] = s1;
    }
}

// ---------------------------------------------------------------------------
// Launch
// ---------------------------------------------------------------------------
extern "C" void kernel_launch(void* const* d_in, const int* in_sizes, int n_in,
                              void* d_out, int out_size)
{
    (void)in_sizes; (void)n_in; (void)out_size;
    const float* hidden   = (const float*)d_in[0];
    const float* residual = (const float*)d_in[1];
    const float* alibi    = (const float*)d_in[2];
    // d_in[3] = attention_mask (pure causal; applied analytically)
    const float* W_qkv    = (const float*)d_in[4];
    const float* b_qkv    = (const float*)d_in[5];
    const float* W_dense  = (const float*)d_in[6];
    const float* b_dense  = (const float*)d_in[7];
    float* out = (float*)d_out;

    __nv_bfloat16 *Ahi, *Alo, *Wqhi, *Wqlo, *Wdhi, *Wdlo, *Chi, *Clo;
    float *ctxp;
    cudaGetSymbolAddress((void**)&Ahi,  g_Ahi);
    cudaGetSymbolAddress((void**)&Alo,  g_Alo);
    cudaGetSymbolAddress((void**)&Wqhi, g_Wqhi);
    cudaGetSymbolAddress((void**)&Wqlo, g_Wqlo);
    cudaGetSymbolAddress((void**)&Wdhi, g_Wdhi);
    cudaGetSymbolAddress((void**)&Wdlo, g_Wdlo);
    cudaGetSymbolAddress((void**)&Chi,  g_Chi);
    cudaGetSymbolAddress((void**)&Clo,  g_Clo);
    cudaGetSymbolAddress((void**)&ctxp, g_ctx);

    // 1) split fp32 operands into bf16 hi/lo
    split_bf16<<<(4096 * 4096) / 1024, 256>>>(hidden,  Ahi,  Alo,  4096 * 4096);
    split_bf16<<<(12288 * 4096) / 1024, 256>>>(W_qkv,  Wqhi, Wqlo, 12288 * 4096);
    split_bf16<<<(4096 * 4096) / 1024, 256>>>(W_dense, Wdhi, Wdlo, 4096 * 4096);

    // 2) QKV projection (HMMA 3-pass split) -> g_q/g_k/g_v
    cudaFuncSetAttribute(hmma_gemm, cudaFuncAttributeMaxDynamicSharedMemorySize,
                         GEMM_SMEM);
    hmma_gemm<<<dim3(32, 96), 256, GEMM_SMEM>>>(Ahi, Alo, Wqhi, Wqlo,
                                                b_qkv, nullptr, nullptr, 4096, 0);

    // 3) attention -> g_ctx
    const int ATTN_SMEM = (3 * 64 * 132 + 64 * 68) * (int)sizeof(float);
    cudaFuncSetAttribute(attn_kernel, cudaFuncAttributeMaxDynamicSharedMemorySize,
                         ATTN_SMEM);
    attn_kernel<<<dim3(Sc / 64, Bc * NHc), 256, ATTN_SMEM>>>(alibi);

    // 4) split ctx, dense projection (+bias +residual) -> out
    split_bf16<<<(4096 * 4096) / 1024, 256>>>(ctxp, Chi, Clo, 4096 * 4096);
    hmma_gemm<<<dim3(32, 32), 256, GEMM_SMEM>>>(Chi, Clo, Wdhi, Wdlo,
                                                b_dense, residual, out, 4096, 1);
}

// round 4
// speedup vs baseline: 1.9439x; 1.1796x over previous
#include <cuda_runtime.h>
#include <cuda_bf16.h>
#include <math.h>
#include <stdint.h>

// ---------------------------------------------------------------------------
// Problem constants
// ---------------------------------------------------------------------------
#define Bc  2
#define Sc  2048
#define Hc  4096
#define NHc 32
#define HDc 128
#define INV_NORM 0.08838834764831845f

// ---------------------------------------------------------------------------
// Device scratch (__device__ globals: allocation-free rule)
// ---------------------------------------------------------------------------
__device__ __align__(256) __nv_bfloat16 g_Ahi[(size_t)4096 * 4096];
__device__ __align__(256) __nv_bfloat16 g_Alo[(size_t)4096 * 4096];
__device__ __align__(256) __nv_bfloat16 g_Wqhi[(size_t)12288 * 4096];
__device__ __align__(256) __nv_bfloat16 g_Wqlo[(size_t)12288 * 4096];
__device__ __align__(256) __nv_bfloat16 g_Wdhi[(size_t)4096 * 4096];
__device__ __align__(256) __nv_bfloat16 g_Wdlo[(size_t)4096 * 4096];
__device__ __align__(256) __nv_bfloat16 g_Chi[(size_t)4096 * 4096];
__device__ __align__(256) __nv_bfloat16 g_Clo[(size_t)4096 * 4096];

// q/k/v as bf16 hi/lo in [B,NH,S,HD]; q pre-scaled by INV_NORM
__device__ __align__(256) __nv_bfloat16 g_qhi[(size_t)Bc * NHc * Sc * HDc];
__device__ __align__(256) __nv_bfloat16 g_qlo[(size_t)Bc * NHc * Sc * HDc];
__device__ __align__(256) __nv_bfloat16 g_khi[(size_t)Bc * NHc * Sc * HDc];
__device__ __align__(256) __nv_bfloat16 g_klo[(size_t)Bc * NHc * Sc * HDc];
__device__ __align__(256) __nv_bfloat16 g_vhi[(size_t)Bc * NHc * Sc * HDc];
__device__ __align__(256) __nv_bfloat16 g_vlo[(size_t)Bc * NHc * Sc * HDc];

// ---------------------------------------------------------------------------
// PTX helpers (sm_80-era only; harness PTX target is plain sm_103)
// ---------------------------------------------------------------------------
__device__ __forceinline__ uint32_t smem_u32(const void* p) {
    uint32_t a;
    asm("{ .reg .u64 t; cvta.to.shared.u64 t, %1; cvt.u32.u64 %0, t; }"
        : "=r"(a) : "l"(p));
    return a;
}
__device__ __forceinline__ void cp16(uint32_t s, const void* g) {
    asm volatile("cp.async.cg.shared.global [%0], [%1], 16;" :: "r"(s), "l"(g));
}
#define CP_COMMIT() asm volatile("cp.async.commit_group;" ::: "memory")
#define CP_WAIT1()  asm volatile("cp.async.wait_group 1;" ::: "memory")
#define CP_WAIT0()  asm volatile("cp.async.wait_group 0;" ::: "memory")

__device__ __forceinline__ void ldsm_x4(uint32_t* r, uint32_t a) {
    asm volatile("ldmatrix.sync.aligned.m8n8.x4.shared.b16 {%0,%1,%2,%3}, [%4];"
        : "=r"(r[0]), "=r"(r[1]), "=r"(r[2]), "=r"(r[3]) : "r"(a));
}
__device__ __forceinline__ void ldsm_x4t(uint32_t* r, uint32_t a) {
    asm volatile("ldmatrix.sync.aligned.m8n8.x4.trans.shared.b16 {%0,%1,%2,%3}, [%4];"
        : "=r"(r[0]), "=r"(r[1]), "=r"(r[2]), "=r"(r[3]) : "r"(a));
}
__device__ __forceinline__ void ldsm_x2(uint32_t* r, uint32_t a) {
    asm volatile("ldmatrix.sync.aligned.m8n8.x2.shared.b16 {%0,%1}, [%2];"
        : "=r"(r[0]), "=r"(r[1]) : "r"(a));
}
__device__ __forceinline__ void mma_bf16(float* c, const uint32_t* a, const uint32_t* b) {
    asm volatile(
        "mma.sync.aligned.m16n8k16.row.col.f32.bf16.bf16.f32 "
        "{%0,%1,%2,%3}, {%4,%5,%6,%7}, {%8,%9}, {%0,%1,%2,%3};"
        : "+f"(c[0]), "+f"(c[1]), "+f"(c[2]), "+f"(c[3])
        : "r"(a[0]), "r"(a[1]), "r"(a[2]), "r"(a[3]), "r"(b[0]), "r"(b[1]));
}
// split two fp32 into packed bf16x2 (hi) and packed bf16x2 residual (lo)
__device__ __forceinline__ void split2(float x0, float x1, uint32_t& hi, uint32_t& lo) {
    __nv_bfloat162 h = __floats2bfloat162_rn(x0, x1);
    __nv_bfloat162 l = __floats2bfloat162_rn(x0 - __low2float(h), x1 - __high2float(h));
    hi = *(uint32_t*)&h;
    lo = *(uint32_t*)&l;
}

// ---------------------------------------------------------------------------
// Kernel: split fp32 -> (hi, lo) bf16 pair
// ---------------------------------------------------------------------------
__global__ __launch_bounds__(256) void split_bf16(
    const float* __restrict__ x,
    __nv_bfloat16* __restrict__ hi,
    __nv_bfloat16* __restrict__ lo,
    int n)
{
    int i = (blockIdx.x * 256 + threadIdx.x) * 4;
    if (i >= n) return;
    float4 v = *(const float4*)(x + i);
    uint32_t h0, l0, h1, l1;
    split2(v.x, v.y, h0, l0);
    split2(v.z, v.w, h1, l1);
    uint32_t* hp = (uint32_t*)(hi + i);
    uint32_t* lp = (uint32_t*)(lo + i);
    hp[0] = h0; hp[1] = h1;
    lp[0] = l0; lp[1] = l1;
}

// ---------------------------------------------------------------------------
// Kernel: HMMA bf16 3-pass split GEMM (2-stage cp.async, 2 CTAs/SM)
//   mode 0: QKV epilogue -> q/k/v bf16 hi/lo (q scaled by INV_NORM)
//   mode 1: dense epilogue (+bias +residual -> out fp32)
// ---------------------------------------------------------------------------
#define BK        32
#define ROWB      80
#define BUF_BYTES (128 * ROWB)   // 10240
#define STG_BYTES (4 * BUF_BYTES)
#define GEMM_SMEM (2 * STG_BYTES) // 81920

__global__ __launch_bounds__(256, 2) void hmma_gemm(
    const __nv_bfloat16* __restrict__ Ahi, const __nv_bfloat16* __restrict__ Alo,
    const __nv_bfloat16* __restrict__ Bhi, const __nv_bfloat16* __restrict__ Blo,
    const float* __restrict__ bias, const float* __restrict__ residual,
    float* __restrict__ out, int K, int mode)
{
    extern __shared__ char smem[];
    const uint32_t sb = smem_u32(smem);
    const int t    = threadIdx.x;
    const int wid  = t >> 5;
    const int lane = t & 31;
    const int wm   = wid >> 2;
    const int wn   = wid & 3;
    const int bm   = blockIdx.x * 128;
    const int bn   = blockIdx.y * 128;
    const int NK   = K / BK;

    float c[4][4][4];
#pragma unroll
    for (int mi = 0; mi < 4; mi++)
#pragma unroll
        for (int ni = 0; ni < 4; ni++)
#pragma unroll
            for (int e = 0; e < 4; e++) c[mi][ni][e] = 0.f;

    const __nv_bfloat16* srcA_hi = Ahi + (size_t)bm * K;
    const __nv_bfloat16* srcA_lo = Alo + (size_t)bm * K;
    const __nv_bfloat16* srcB_hi = Bhi + (size_t)bn * K;
    const __nv_bfloat16* srcB_lo = Blo + (size_t)bn * K;

    auto load_stage = [&](int st, int k0) {
        uint32_t s0 = sb + (uint32_t)st * STG_BYTES;
        const __nv_bfloat16* srcs[4] = { srcA_hi, srcA_lo, srcB_hi, srcB_lo };
#pragma unroll
        for (int bfi = 0; bfi < 4; bfi++) {
#pragma unroll
            for (int u = 0; u < 2; u++) {
                int id = u * 256 + t;
                int r  = id >> 2, cc = id & 3;
                cp16(s0 + (uint32_t)bfi * BUF_BYTES + (uint32_t)(r * ROWB + cc * 16),
                     srcs[bfi] + (size_t)r * K + k0 + cc * 8);
            }
        }
        CP_COMMIT();
    };

    load_stage(0, 0);

    const int a_row  = (lane & 15);
    const int a_coff = (lane >> 4) * 16;
    const int b_row  = (lane & 7);
    const int b_coff = ((lane >> 3) & 1) * 16;

    for (int i = 0; i < NK; ++i) {
        if (i + 1 < NK) { load_stage((i + 1) & 1, (i + 1) * BK); CP_WAIT1(); }
        else            { CP_WAIT0(); }
        __syncthreads();

        const uint32_t sbase = sb + (uint32_t)(i & 1) * STG_BYTES;
        const uint32_t sa = sbase + (uint32_t)(wm * 64) * ROWB;
        const uint32_t sB = sbase + 2u * BUF_BYTES + (uint32_t)(wn * 32) * ROWB;
#pragma unroll
        for (int kb = 0; kb < 2; ++kb) {
            const int kcol = kb * 32;
            uint32_t bh[4][2], bl[4][2];
#pragma unroll
            for (int ni = 0; ni < 4; ++ni) {
                uint32_t addr = sB + (uint32_t)((ni * 8 + b_row) * ROWB + kcol + b_coff);
                ldsm_x2(bh[ni], addr);
                ldsm_x2(bl[ni], addr + BUF_BYTES);
            }
#pragma unroll
            for (int mi = 0; mi < 4; ++mi) {
                uint32_t ah[4], al[4];
                uint32_t addr = sa + (uint32_t)((mi * 16 + a_row) * ROWB + kcol + a_coff);
                ldsm_x4(ah, addr);
                ldsm_x4(al, addr + BUF_BYTES);
#pragma unroll
                for (int ni = 0; ni < 4; ++ni) {
                    mma_bf16(c[mi][ni], ah, bh[ni]);
                    mma_bf16(c[mi][ni], ah, bl[ni]);
                    mma_bf16(c[mi][ni], al, bh[ni]);
                }
            }
        }
        __syncthreads();
    }

    // ---- epilogue ----
    const int qr = lane >> 2;
    const int qc = (lane & 3) * 2;

    if (mode == 0) {
        const int nh    = bn / 384;
        const int which = (bn % 384) >> 7;
        __nv_bfloat16 *dhi, *dlo;
        if      (which == 0) { dhi = g_qhi; dlo = g_qlo; }
        else if (which == 1) { dhi = g_khi; dlo = g_klo; }
        else                 { dhi = g_vhi; dlo = g_vlo; }
        const float scale = (which == 0) ? INV_NORM : 1.0f;
#pragma unroll
        for (int mi = 0; mi < 4; ++mi) {
#pragma unroll
            for (int rr = 0; rr < 2; ++rr) {
                int m = bm + wm * 64 + mi * 16 + qr + rr * 8;
                int b = m >> 11, ss = m & 2047;
                size_t rowoff = (((size_t)b * NHc + nh) * Sc + ss) * HDc;
#pragma unroll
                for (int ni = 0; ni < 4; ++ni) {
                    int hd = wn * 32 + ni * 8 + qc;
                    float x0 = (c[mi][ni][rr * 2 + 0] + __ldg(&bias[bn + hd]))     * scale;
                    float x1 = (c[mi][ni][rr * 2 + 1] + __ldg(&bias[bn + hd + 1])) * scale;
                    uint32_t hbits, lbits;
                    split2(x0, x1, hbits, lbits);
                    *(uint32_t*)(dhi + rowoff + hd) = hbits;
                    *(uint32_t*)(dlo + rowoff + hd) = lbits;
                }
            }
        }
    } else {
#pragma unroll
        for (int mi = 0; mi < 4; ++mi) {
#pragma unroll
            for (int rr = 0; rr < 2; ++rr) {
                int m = bm + wm * 64 + mi * 16 + qr + rr * 8;
#pragma unroll
                for (int ni = 0; ni < 4; ++ni) {
                    int n = bn + wn * 32 + ni * 8 + qc;
                    size_t o = (size_t)m * Hc + n;
                    float2 rv = *(const float2*)(residual + o);
                    float2 v;
                    v.x = c[mi][ni][rr * 2 + 0] + __ldg(&bias[n])     + rv.x;
                    v.y = c[mi][ni][rr * 2 + 1] + __ldg(&bias[n + 1]) + rv.y;
                    *(float2*)(out + o) = v;
                }
            }
        }
    }
}

// ---------------------------------------------------------------------------
// Kernel: MMA flash attention (3-pass split bf16), ALiBi + causal.
//   grid = (16, 64): x -> q-tile (reversed for load balance), y -> b*NH+nh
//   CTA: 8 warps, q-tile 128 rows; warp wq owns rows [wq*16, wq*16+16).
//   k-tiles of 64 keys, double-buffered cp.async (Khi,Klo,Vhi,Vlo).
//   Writes ctx directly as bf16 hi/lo (g_Chi/g_Clo) in [B,S,H].
// ---------------------------------------------------------------------------
#define KROWB 272
#define KBUF  (64 * KROWB)          // 17408
#define KSTG  (4 * KBUF)            // 69632
#define QBUF  (128 * KROWB)         // 34816
#define ATTN_SMEM (2 * QBUF + 2 * KSTG)  // 208896

__global__ __launch_bounds__(256, 1) void attn_mma(const float* __restrict__ alibi)
{
    extern __shared__ char smem[];
    const uint32_t sb   = smem_u32(smem);
    const uint32_t qsm  = sb;
    const uint32_t kvsm = sb + 2 * QBUF;

    const int t    = threadIdx.x;
    const int wq   = t >> 5;
    const int lane = t & 31;
    const int qt   = 15 - blockIdx.x;          // heavy tiles first
    const int bh   = blockIdx.y;
    const int q0   = qt * 128;

    // ---- Q tile load (hi, lo), group 1
    {
        const __nv_bfloat16* qh = g_qhi + ((size_t)bh * Sc + q0) * HDc;
        const __nv_bfloat16* ql = g_qlo + ((size_t)bh * Sc + q0) * HDc;
#pragma unroll
        for (int u = 0; u < 8; ++u) {
            int id = u * 256 + t;            // 0..2047
            int r = id >> 4, cc = id & 15;
            cp16(qsm + (uint32_t)(r * KROWB + cc * 16), qh + (size_t)r * 128 + cc * 8);
            cp16(qsm + QBUF + (uint32_t)(r * KROWB + cc * 16), ql + (size_t)r * 128 + cc * 8);
        }
        CP_COMMIT();
    }

    auto load_kv = [&](int st, int kt) {
        uint32_t d0 = kvsm + (uint32_t)st * KSTG;
        size_t goff = ((size_t)bh * Sc + (size_t)kt * 64) * HDc;
        const __nv_bfloat16* srcs[4] = { g_khi + goff, g_klo + goff,
                                         g_vhi + goff, g_vlo + goff };
#pragma unroll
        for (int buf = 0; buf < 4; ++buf) {
#pragma unroll
            for (int u = 0; u < 4; ++u) {
                int id = u * 256 + t;        // 0..1023
                int r = id >> 4, cc = id & 15;
                cp16(d0 + (uint32_t)buf * KBUF + (uint32_t)(r * KROWB + cc * 16),
                     srcs[buf] + (size_t)r * 128 + cc * 8);
            }
        }
        CP_COMMIT();
    };

    load_kv(0, 0);

    float o[16][4];
#pragma unroll
    for (int nn = 0; nn < 16; ++nn)
#pragma unroll
        for (int e = 0; e < 4; ++e) o[nn][e] = 0.f;
    float m0 = -INFINITY, m1 = -INFINITY, l0 = 0.f, l1 = 0.f;

    const float* al = alibi + (size_t)bh * Sc;
    const int qg0 = q0 + wq * 16 + (lane >> 2);
    const int ktmax = 2 * qt + 1;

    for (int kt = 0; kt <= ktmax; ++kt) {
        if (kt < ktmax) { load_kv((kt + 1) & 1, kt + 1); CP_WAIT1(); }
        else            { CP_WAIT0(); }
        __syncthreads();

        const uint32_t st = kvsm + (uint32_t)(kt & 1) * KSTG;

        // ---- S = Q K^T (3-pass split), S frags s[8][4]
        float s[8][4];
#pragma unroll
        for (int ni = 0; ni < 8; ++ni)
#pragma unroll
            for (int e = 0; e < 4; ++e) s[ni][e] = 0.f;

#pragma unroll
        for (int kk = 0; kk < 8; ++kk) {
            uint32_t qh[4], ql[4];
            uint32_t qa = qsm + (uint32_t)((wq * 16 + (lane & 15)) * KROWB
                        + kk * 32 + ((lane >> 4) & 1) * 16);
            ldsm_x4(qh, qa);
            ldsm_x4(ql, qa + QBUF);
#pragma unroll
            for (int nip = 0; nip < 4; ++nip) {
                uint32_t kh[4], kl[4];
                uint32_t ka = st + (uint32_t)((nip * 16 + ((lane >> 4) & 1) * 8 + (lane & 7)) * KROWB
                            + kk * 32 + ((lane >> 3) & 1) * 16);
                ldsm_x4(kh, ka);
                ldsm_x4(kl, ka + KBUF);
                mma_bf16(s[2 * nip],     qh, &kh[0]);
                mma_bf16(s[2 * nip],     qh, &kl[0]);
                mma_bf16(s[2 * nip],     ql, &kh[0]);
                mma_bf16(s[2 * nip + 1], qh, &kh[2]);
                mma_bf16(s[2 * nip + 1], qh, &kl[2]);
                mma_bf16(s[2 * nip + 1], ql, &kh[2]);
            }
        }

        // ---- alibi + causal mask
        const int ktb = kt * 64;
        const bool msk = (kt >= 2 * qt);
#pragma unroll
        for (int ni = 0; ni < 8; ++ni) {
            int key = ktb + ni * 8 + 2 * (lane & 3);
            float a0 = __ldg(al + key);
            float a1 = __ldg(al + key + 1);
            s[ni][0] += a0; s[ni][1] += a1;
            s[ni][2] += a0; s[ni][3] += a1;
            if (msk) {
                if (key     > qg0)     s[ni][0] = -1e30f;
                if (key + 1 > qg0)     s[ni][1] = -1e30f;
                if (key     > qg0 + 8) s[ni][2] = -1e30f;
                if (key + 1 > qg0 + 8) s[ni][3] = -1e30f;
            }
        }

        // ---- online softmax (rows qg0, qg0+8 per lane)
        float mx0 = -INFINITY, mx1 = -INFINITY;
#pragma unroll
        for (int ni = 0; ni < 8; ++ni) {
            mx0 = fmaxf(mx0, fmaxf(s[ni][0], s[ni][1]));
            mx1 = fmaxf(mx1, fmaxf(s[ni][2], s[ni][3]));
        }
        mx0 = fmaxf(mx0, __shfl_xor_sync(0xffffffffu, mx0, 1));
        mx0 = fmaxf(mx0, __shfl_xor_sync(0xffffffffu, mx0, 2));
        mx1 = fmaxf(mx1, __shfl_xor_sync(0xffffffffu, mx1, 1));
        mx1 = fmaxf(mx1, __shfl_xor_sync(0xffffffffu, mx1, 2));
        float m0n = fmaxf(m0, mx0), m1n = fmaxf(m1, mx1);
        float c0 = __expf(m0 - m0n), c1 = __expf(m1 - m1n);
        float ps0 = 0.f, ps1 = 0.f;
#pragma unroll
        for (int ni = 0; ni < 8; ++ni) {
            s[ni][0] = __expf(s[ni][0] - m0n);
            s[ni][1] = __expf(s[ni][1] - m0n);
            s[ni][2] = __expf(s[ni][2] - m1n);
            s[ni][3] = __expf(s[ni][3] - m1n);
            ps0 += s[ni][0] + s[ni][1];
            ps1 += s[ni][2] + s[ni][3];
        }
        ps0 += __shfl_xor_sync(0xffffffffu, ps0, 1);
        ps0 += __shfl_xor_sync(0xffffffffu, ps0, 2);
        ps1 += __shfl_xor_sync(0xffffffffu, ps1, 1);
        ps1 += __shfl_xor_sync(0xffffffffu, ps1, 2);
        l0 = l0 * c0 + ps0;
        l1 = l1 * c1 + ps1;
        m0 = m0n; m1 = m1n;
#pragma unroll
        for (int nn = 0; nn < 16; ++nn) {
            o[nn][0] *= c0; o[nn][1] *= c0;
            o[nn][2] *= c1; o[nn][3] *= c1;
        }

        // ---- O += P V (3-pass split; P packed from S frags in registers)
        const uint32_t vbase = st + 2u * KBUF;
#pragma unroll
        for (int kk2 = 0; kk2 < 4; ++kk2) {
            uint32_t pah[4], pal[4];
            split2(s[2 * kk2][0],     s[2 * kk2][1],     pah[0], pal[0]);
            split2(s[2 * kk2][2],     s[2 * kk2][3],     pah[1], pal[1]);
            split2(s[2 * kk2 + 1][0], s[2 * kk2 + 1][1], pah[2], pal[2]);
            split2(s[2 * kk2 + 1][2], s[2 * kk2 + 1][3], pah[3], pal[3]);
#pragma unroll
            for (int nn8 = 0; nn8 < 8; ++nn8) {
                uint32_t vh[4], vl[4];
                uint32_t va = vbase + (uint32_t)((kk2 * 16 + (lane & 15)) * KROWB
                            + nn8 * 32 + ((lane >> 4) & 1) * 16);
                ldsm_x4t(vh, va);
                ldsm_x4t(vl, va + KBUF);
                mma_bf16(o[2 * nn8],     pah, &vh[0]);
                mma_bf16(o[2 * nn8],     pah, &vl[0]);
                mma_bf16(o[2 * nn8],     pal, &vh[0]);
                mma_bf16(o[2 * nn8 + 1], pah, &vh[2]);
                mma_bf16(o[2 * nn8 + 1], pah, &vl[2]);
                mma_bf16(o[2 * nn8 + 1], pal, &vh[2]);
            }
        }
        __syncthreads();
    }

    // ---- normalize, split to bf16 hi/lo, write ctx [B,S,H]
    const float inv0 = 1.f / l0;
    const float inv1 = 1.f / l1;
    const int b  = bh >> 5;
    const int nh = bh & 31;
    const int row0 = q0 + wq * 16 + (lane >> 2);
#pragma unroll
    for (int nn = 0; nn < 16; ++nn) {
        int hd = nn * 8 + 2 * (lane & 3);
        size_t o0 = ((size_t)(b * Sc + row0)) * Hc + nh * HDc + hd;
        size_t o1 = o0 + 8 * (size_t)Hc;
        uint32_t hbits, lbits;
        split2(o[nn][0] * inv0, o[nn][1] * inv0, hbits, lbits);
        *(uint32_t*)(g_Chi + o0) = hbits;
        *(uint32_t*)(g_Clo + o0) = lbits;
        split2(o[nn][2] * inv1, o[nn][3] * inv1, hbits, lbits);
        *(uint32_t*)(g_Chi + o1) = hbits;
        *(uint32_t*)(g_Clo + o1) = lbits;
    }
}

// ---------------------------------------------------------------------------
// Launch
// ---------------------------------------------------------------------------
extern "C" void kernel_launch(void* const* d_in, const int* in_sizes, int n_in,
                              void* d_out, int out_size)
{
    (void)in_sizes; (void)n_in; (void)out_size;
    const float* hidden   = (const float*)d_in[0];
    const float* residual = (const float*)d_in[1];
    const float* alibi    = (const float*)d_in[2];
    // d_in[3] = attention_mask (pure causal; applied analytically)
    const float* W_qkv    = (const float*)d_in[4];
    const float* b_qkv    = (const float*)d_in[5];
    const float* W_dense  = (const float*)d_in[6];
    const float* b_dense  = (const float*)d_in[7];
    float* out = (float*)d_out;

    __nv_bfloat16 *Ahi, *Alo, *Wqhi, *Wqlo, *Wdhi, *Wdlo, *Chi, *Clo;
    cudaGetSymbolAddress((void**)&Ahi,  g_Ahi);
    cudaGetSymbolAddress((void**)&Alo,  g_Alo);
    cudaGetSymbolAddress((void**)&Wqhi, g_Wqhi);
    cudaGetSymbolAddress((void**)&Wqlo, g_Wqlo);
    cudaGetSymbolAddress((void**)&Wdhi, g_Wdhi);
    cudaGetSymbolAddress((void**)&Wdlo, g_Wdlo);
    cudaGetSymbolAddress((void**)&Chi,  g_Chi);
    cudaGetSymbolAddress((void**)&Clo,  g_Clo);

    // 1) split fp32 operands into bf16 hi/lo
    split_bf16<<<(4096 * 4096) / 1024, 256>>>(hidden,  Ahi,  Alo,  4096 * 4096);
    split_bf16<<<(12288 * 4096) / 1024, 256>>>(W_qkv,  Wqhi, Wqlo, 12288 * 4096);
    split_bf16<<<(4096 * 4096) / 1024, 256>>>(W_dense, Wdhi, Wdlo, 4096 * 4096);

    // 2) QKV projection -> q/k/v bf16 hi/lo (q pre-scaled)
    cudaFuncSetAttribute(hmma_gemm, cudaFuncAttributeMaxDynamicSharedMemorySize,
                         GEMM_SMEM);
    hmma_gemm<<<dim3(32, 96), 256, GEMM_SMEM>>>(Ahi, Alo, Wqhi, Wqlo,
                                                b_qkv, nullptr, nullptr, 4096, 0);

    // 3) MMA flash attention -> ctx bf16 hi/lo (g_Chi/g_Clo)
    cudaFuncSetAttribute(attn_mma, cudaFuncAttributeMaxDynamicSharedMemorySize,
                         ATTN_SMEM);
    attn_mma<<<dim3(16, 64), 256, ATTN_SMEM>>>(alibi);

    // 4) dense projection (+bias +residual) -> out
    hmma_gemm<<<dim3(32, 32), 256, GEMM_SMEM>>>(Chi, Clo, Wdhi, Wdlo,
                                                b_dense, residual, out, 4096, 1);
}

// round 6
// speedup vs baseline: 3.6829x; 1.8946x over previous
#include <cuda_runtime.h>
#include <cuda_bf16.h>
#include <cuda_fp16.h>
#include <math.h>
#include <stdint.h>

// ---------------------------------------------------------------------------
// Problem constants
// ---------------------------------------------------------------------------
#define Bc  2
#define Sc  2048
#define Hc  4096
#define NHc 32
#define HDc 128
#define INV_NORM 0.08838834764831845f

// ---------------------------------------------------------------------------
// Device scratch (__device__ globals: allocation-free rule)
// ---------------------------------------------------------------------------
__device__ __align__(256) __nv_bfloat16 g_Ahi[(size_t)4096 * 4096];
__device__ __align__(256) __nv_bfloat16 g_Alo[(size_t)4096 * 4096];
__device__ __align__(256) __nv_bfloat16 g_Wqhi[(size_t)12288 * 4096];
__device__ __align__(256) __nv_bfloat16 g_Wqlo[(size_t)12288 * 4096];
__device__ __align__(256) __nv_bfloat16 g_Wdhi[(size_t)4096 * 4096];
__device__ __align__(256) __nv_bfloat16 g_Wdlo[(size_t)4096 * 4096];
__device__ __align__(256) __nv_bfloat16 g_Chi[(size_t)4096 * 4096];
__device__ __align__(256) __nv_bfloat16 g_Clo[(size_t)4096 * 4096];

// attention operands in fp16: q split (pre-scaled by INV_NORM), k pure, v split
__device__ __align__(256) __half g_qhi[(size_t)Bc * NHc * Sc * HDc];
__device__ __align__(256) __half g_qlo[(size_t)Bc * NHc * Sc * HDc];
__device__ __align__(256) __half g_khi[(size_t)Bc * NHc * Sc * HDc];
__device__ __align__(256) __half g_vhi[(size_t)Bc * NHc * Sc * HDc];
__device__ __align__(256) __half g_vlo[(size_t)Bc * NHc * Sc * HDc];

// ---------------------------------------------------------------------------
// PTX helpers (sm_80-era only; harness PTX target is plain sm_103)
// ---------------------------------------------------------------------------
__device__ __forceinline__ uint32_t smem_u32(const void* p) {
    uint32_t a;
    asm("{ .reg .u64 t; cvta.to.shared.u64 t, %1; cvt.u32.u64 %0, t; }"
        : "=r"(a) : "l"(p));
    return a;
}
__device__ __forceinline__ void cp16(uint32_t s, const void* g) {
    asm volatile("cp.async.cg.shared.global [%0], [%1], 16;" :: "r"(s), "l"(g));
}
#define CP_COMMIT() asm volatile("cp.async.commit_group;" ::: "memory")
#define CP_WAIT1()  asm volatile("cp.async.wait_group 1;" ::: "memory")
#define CP_WAIT0()  asm volatile("cp.async.wait_group 0;" ::: "memory")

__device__ __forceinline__ void ldsm_x4(uint32_t* r, uint32_t a) {
    asm volatile("ldmatrix.sync.aligned.m8n8.x4.shared.b16 {%0,%1,%2,%3}, [%4];"
        : "=r"(r[0]), "=r"(r[1]), "=r"(r[2]), "=r"(r[3]) : "r"(a));
}
__device__ __forceinline__ void ldsm_x4t(uint32_t* r, uint32_t a) {
    asm volatile("ldmatrix.sync.aligned.m8n8.x4.trans.shared.b16 {%0,%1,%2,%3}, [%4];"
        : "=r"(r[0]), "=r"(r[1]), "=r"(r[2]), "=r"(r[3]) : "r"(a));
}
__device__ __forceinline__ void ldsm_x2(uint32_t* r, uint32_t a) {
    asm volatile("ldmatrix.sync.aligned.m8n8.x2.shared.b16 {%0,%1}, [%2];"
        : "=r"(r[0]), "=r"(r[1]) : "r"(a));
}
__device__ __forceinline__ void mma_bf16(float* c, const uint32_t* a, const uint32_t* b) {
    asm volatile(
        "mma.sync.aligned.m16n8k16.row.col.f32.bf16.bf16.f32 "
        "{%0,%1,%2,%3}, {%4,%5,%6,%7}, {%8,%9}, {%0,%1,%2,%3};"
        : "+f"(c[0]), "+f"(c[1]), "+f"(c[2]), "+f"(c[3])
        : "r"(a[0]), "r"(a[1]), "r"(a[2]), "r"(a[3]), "r"(b[0]), "r"(b[1]));
}
__device__ __forceinline__ void mma_fp16(float* c, const uint32_t* a, const uint32_t* b) {
    asm volatile(
        "mma.sync.aligned.m16n8k16.row.col.f32.f16.f16.f32 "
        "{%0,%1,%2,%3}, {%4,%5,%6,%7}, {%8,%9}, {%0,%1,%2,%3};"
        : "+f"(c[0]), "+f"(c[1]), "+f"(c[2]), "+f"(c[3])
        : "r"(a[0]), "r"(a[1]), "r"(a[2]), "r"(a[3]), "r"(b[0]), "r"(b[1]));
}
// bf16 hi/lo split of two fp32 (packed)
__device__ __forceinline__ void split2(float x0, float x1, uint32_t& hi, uint32_t& lo) {
    __nv_bfloat162 h = __floats2bfloat162_rn(x0, x1);
    __nv_bfloat162 l = __floats2bfloat162_rn(x0 - __low2float(h), x1 - __high2float(h));
    hi = *(uint32_t*)&h;
    lo = *(uint32_t*)&l;
}
// fp16 hi/lo split of two fp32 (packed)
__device__ __forceinline__ void split2h(float x0, float x1, uint32_t& hi, uint32_t& lo) {
    __half2 h = __floats2half2_rn(x0, x1);
    __half2 l = __floats2half2_rn(x0 - __low2float(h), x1 - __high2float(h));
    hi = *(uint32_t*)&h;
    lo = *(uint32_t*)&l;
}
__device__ __forceinline__ uint32_t pack_h2(float x0, float x1) {
    __half2 h = __floats2half2_rn(x0, x1);
    return *(uint32_t*)&h;
}

// ---------------------------------------------------------------------------
// Kernel: split fp32 -> (hi, lo) bf16 pair
// ---------------------------------------------------------------------------
__global__ __launch_bounds__(256) void split_bf16(
    const float* __restrict__ x,
    __nv_bfloat16* __restrict__ hi,
    __nv_bfloat16* __restrict__ lo,
    int n)
{
    int i = (blockIdx.x * 256 + threadIdx.x) * 4;
    if (i >= n) return;
    float4 v = *(const float4*)(x + i);
    uint32_t h0, l0, h1, l1;
    split2(v.x, v.y, h0, l0);
    split2(v.z, v.w, h1, l1);
    uint32_t* hp = (uint32_t*)(hi + i);
    uint32_t* lp = (uint32_t*)(lo + i);
    hp[0] = h0; hp[1] = h1;
    lp[0] = l0; lp[1] = l1;
}

// ---------------------------------------------------------------------------
// Kernel: HMMA bf16 3-pass split GEMM.
//   Compact XOR-swizzled smem (64B rows), 3-stage cp.async, ONE sync/iter,
//   2 CTAs/SM. C[128x128] = A[M,K] * B[N,K]^T, fp32 accum.
//   mode 0: QKV epilogue -> q (fp16 hi/lo, scaled), k (fp16), v (fp16 hi/lo)
//   mode 1: dense epilogue (+bias +residual -> out fp32)
// ---------------------------------------------------------------------------
#define BK        32
#define GBUF      8192              // 128 rows x 64B
#define STG_BYTES (4 * GBUF)        // Ahi, Alo, Bhi, Blo = 32KB
#define GEMM_SMEM (3 * STG_BYTES)   // 98304

// swizzled address: row r (64B apart), 16B-chunk c in 0..3
__device__ __forceinline__ uint32_t swz(uint32_t base, int r, int c) {
    return base + (uint32_t)(r * 64 + ((c ^ ((r >> 1) & 3)) << 4));
}

__global__ __launch_bounds__(256, 2) void hmma_gemm(
    const __nv_bfloat16* __restrict__ Ahi, const __nv_bfloat16* __restrict__ Alo,
    const __nv_bfloat16* __restrict__ Bhi, const __nv_bfloat16* __restrict__ Blo,
    const float* __restrict__ bias, const float* __restrict__ residual,
    float* __restrict__ out, int K, int mode)
{
    extern __shared__ char smem[];
    const uint32_t sb = smem_u32(smem);
    const int t    = threadIdx.x;
    const int wid  = t >> 5;
    const int lane = t & 31;
    const int wm   = wid >> 2;
    const int wn   = wid & 3;
    const int bm   = blockIdx.x * 128;
    const int bn   = blockIdx.y * 128;
    const int NK   = K / BK;

    float c[4][4][4];
#pragma unroll
    for (int mi = 0; mi < 4; mi++)
#pragma unroll
        for (int ni = 0; ni < 4; ni++)
#pragma unroll
            for (int e = 0; e < 4; e++) c[mi][ni][e] = 0.f;

    const __nv_bfloat16* srcs[4] = { Ahi + (size_t)bm * K, Alo + (size_t)bm * K,
                                     Bhi + (size_t)bn * K, Blo + (size_t)bn * K };

    auto load_stage = [&](int st, int k0) {
        uint32_t s0 = sb + (uint32_t)st * STG_BYTES;
#pragma unroll
        for (int bfi = 0; bfi < 4; bfi++) {
#pragma unroll
            for (int u = 0; u < 2; u++) {
                int id = u * 256 + t;
                int r  = id >> 2, cc = id & 3;
                cp16(swz(s0 + (uint32_t)bfi * GBUF, r, cc),
                     srcs[bfi] + (size_t)r * K + k0 + cc * 8);
            }
        }
        CP_COMMIT();
    };

    load_stage(0, 0);
    load_stage(1, BK);

    const int ra  = (lane & 15);
    const int ca0 = (lane >> 4);
    const int rb  = (lane & 7);
    const int cb0 = ((lane >> 3) & 1);

    int st = 0;
    for (int i = 0; i < NK; ++i) {
        if (i == NK - 1) CP_WAIT0(); else CP_WAIT1();
        __syncthreads();
        if (i + 2 < NK) {
            int st2 = st + 2;
            if (st2 >= 3) st2 -= 3;          // FIXED ring successor
            load_stage(st2, (i + 2) * BK);
        }

        const uint32_t sbase = sb + (uint32_t)st * STG_BYTES;
#pragma unroll
        for (int kb = 0; kb < 2; ++kb) {
            uint32_t bh[4][2], bl[4][2];
#pragma unroll
            for (int ni = 0; ni < 4; ++ni) {
                uint32_t addr = swz(sbase + 2u * GBUF, wn * 32 + ni * 8 + rb, kb * 2 + cb0);
                ldsm_x2(bh[ni], addr);
                ldsm_x2(bl[ni], addr + GBUF);
            }
#pragma unroll
            for (int mi = 0; mi < 4; ++mi) {
                uint32_t ah[4], al[4];
                uint32_t addr = swz(sbase, wm * 64 + mi * 16 + ra, kb * 2 + ca0);
                ldsm_x4(ah, addr);
                ldsm_x4(al, addr + GBUF);
#pragma unroll
                for (int ni = 0; ni < 4; ++ni) {
                    mma_bf16(c[mi][ni], ah, bh[ni]);
                    mma_bf16(c[mi][ni], ah, bl[ni]);
                    mma_bf16(c[mi][ni], al, bh[ni]);
                }
            }
        }
        st = (st + 1 == 3) ? 0 : st + 1;
    }

    // ---- epilogue ----
    const int qr = lane >> 2;
    const int qc = (lane & 3) * 2;

    if (mode == 0) {
        const int nh    = bn / 384;
        const int which = (bn % 384) >> 7;
        const float scale = (which == 0) ? INV_NORM : 1.0f;
        __half *dhi = (which == 0) ? g_qhi : g_vhi;
        __half *dlo = (which == 0) ? g_qlo : g_vlo;
#pragma unroll
        for (int mi = 0; mi < 4; ++mi) {
#pragma unroll
            for (int rr = 0; rr < 2; ++rr) {
                int m = bm + wm * 64 + mi * 16 + qr + rr * 8;
                int b = m >> 11, ss = m & 2047;
                size_t rowoff = (((size_t)b * NHc + nh) * Sc + ss) * HDc;
#pragma unroll
                for (int ni = 0; ni < 4; ++ni) {
                    int hd = wn * 32 + ni * 8 + qc;
                    float x0 = (c[mi][ni][rr * 2 + 0] + __ldg(&bias[bn + hd]))     * scale;
                    float x1 = (c[mi][ni][rr * 2 + 1] + __ldg(&bias[bn + hd + 1])) * scale;
                    if (which == 1) {
                        *(uint32_t*)(g_khi + rowoff + hd) = pack_h2(x0, x1);
                    } else {
                        uint32_t hb, lb;
                        split2h(x0, x1, hb, lb);
                        *(uint32_t*)(dhi + rowoff + hd) = hb;
                        *(uint32_t*)(dlo + rowoff + hd) = lb;
                    }
                }
            }
        }
    } else {
#pragma unroll
        for (int mi = 0; mi < 4; ++mi) {
#pragma unroll
            for (int rr = 0; rr < 2; ++rr) {
                int m = bm + wm * 64 + mi * 16 + qr + rr * 8;
#pragma unroll
                for (int ni = 0; ni < 4; ++ni) {
                    int n = bn + wn * 32 + ni * 8 + qc;
                    size_t o = (size_t)m * Hc + n;
                    float2 rv = *(const float2*)(residual + o);
                    float2 v;
                    v.x = c[mi][ni][rr * 2 + 0] + __ldg(&bias[n])     + rv.x;
                    v.y = c[mi][ni][rr * 2 + 1] + __ldg(&bias[n + 1]) + rv.y;
                    *(float2*)(out + o) = v;
                }
            }
        }
    }
}

// ---------------------------------------------------------------------------
// Kernel: MMA flash attention, fp16 2-pass (Q split x K pure; P pure x V split)
//   grid = (16, 64); CTA: 8 warps, q-tile 128; k-tiles 64, double-buffered.
//   Writes ctx as bf16 hi/lo (g_Chi/g_Clo) for the 3-pass dense GEMM.
// ---------------------------------------------------------------------------
#define KROWB 272
#define KBUF  (64 * KROWB)           // 17408
#define KSTG  (3 * KBUF)             // khi, vhi, vlo = 52224
#define QBUF  (128 * KROWB)          // 34816
#define ATTN_SMEM (2 * QBUF + 2 * KSTG)  // 174080

__global__ __launch_bounds__(256, 1) void attn_mma(const float* __restrict__ alibi)
{
    extern __shared__ char smem[];
    const uint32_t sb   = smem_u32(smem);
    const uint32_t qsm  = sb;
    const uint32_t kvsm = sb + 2 * QBUF;

    const int t    = threadIdx.x;
    const int wq   = t >> 5;
    const int lane = t & 31;
    const int qt   = 15 - blockIdx.x;          // heavy tiles first
    const int bh   = blockIdx.y;
    const int q0   = qt * 128;

    // ---- Q tile load (hi, lo)
    {
        const __half* qh = g_qhi + ((size_t)bh * Sc + q0) * HDc;
        const __half* ql = g_qlo + ((size_t)bh * Sc + q0) * HDc;
#pragma unroll
        for (int u = 0; u < 8; ++u) {
            int id = u * 256 + t;
            int r = id >> 4, cc = id & 15;
            cp16(qsm + (uint32_t)(r * KROWB + cc * 16), qh + (size_t)r * 128 + cc * 8);
            cp16(qsm + QBUF + (uint32_t)(r * KROWB + cc * 16), ql + (size_t)r * 128 + cc * 8);
        }
        CP_COMMIT();
    }

    auto load_kv = [&](int st, int kt) {
        uint32_t d0 = kvsm + (uint32_t)st * KSTG;
        size_t goff = ((size_t)bh * Sc + (size_t)kt * 64) * HDc;
        const __half* srcs[3] = { g_khi + goff, g_vhi + goff, g_vlo + goff };
#pragma unroll
        for (int buf = 0; buf < 3; ++buf) {
#pragma unroll
            for (int u = 0; u < 4; ++u) {
                int id = u * 256 + t;
                int r = id >> 4, cc = id & 15;
                cp16(d0 + (uint32_t)buf * KBUF + (uint32_t)(r * KROWB + cc * 16),
                     srcs[buf] + (size_t)r * 128 + cc * 8);
            }
        }
        CP_COMMIT();
    };

    load_kv(0, 0);

    float o[16][4];
#pragma unroll
    for (int nn = 0; nn < 16; ++nn)
#pragma unroll
        for (int e = 0; e < 4; ++e) o[nn][e] = 0.f;
    float m0 = -INFINITY, m1 = -INFINITY, l0 = 0.f, l1 = 0.f;

    const float* al = alibi + (size_t)bh * Sc;
    const int qg0 = q0 + wq * 16 + (lane >> 2);
    const int ktmax = 2 * qt + 1;

    for (int kt = 0; kt <= ktmax; ++kt) {
        if (kt < ktmax) { load_kv((kt + 1) & 1, kt + 1); CP_WAIT1(); }
        else            { CP_WAIT0(); }
        __syncthreads();

        const uint32_t st = kvsm + (uint32_t)(kt & 1) * KSTG;

        // ---- S = Q K^T : Qhi*K + Qlo*K (fp16 2-pass)
        float s[8][4];
#pragma unroll
        for (int ni = 0; ni < 8; ++ni)
#pragma unroll
            for (int e = 0; e < 4; ++e) s[ni][e] = 0.f;

#pragma unroll
        for (int kk = 0; kk < 8; ++kk) {
            uint32_t qh[4], ql[4];
            uint32_t qa = qsm + (uint32_t)((wq * 16 + (lane & 15)) * KROWB
                        + kk * 32 + ((lane >> 4) & 1) * 16);
            ldsm_x4(qh, qa);
            ldsm_x4(ql, qa + QBUF);
#pragma unroll
            for (int nip = 0; nip < 4; ++nip) {
                uint32_t kh[4];
                uint32_t ka = st + (uint32_t)((nip * 16 + ((lane >> 4) & 1) * 8 + (lane & 7)) * KROWB
                            + kk * 32 + ((lane >> 3) & 1) * 16);
                ldsm_x4(kh, ka);
                mma_fp16(s[2 * nip],     qh, &kh[0]);
                mma_fp16(s[2 * nip],     ql, &kh[0]);
                mma_fp16(s[2 * nip + 1], qh, &kh[2]);
                mma_fp16(s[2 * nip + 1], ql, &kh[2]);
            }
        }

        // ---- alibi + causal mask
        const int ktb = kt * 64;
        const bool msk = (kt >= 2 * qt);
#pragma unroll
        for (int ni = 0; ni < 8; ++ni) {
            int key = ktb + ni * 8 + 2 * (lane & 3);
            float a0 = __ldg(al + key);
            float a1 = __ldg(al + key + 1);
            s[ni][0] += a0; s[ni][1] += a1;
            s[ni][2] += a0; s[ni][3] += a1;
            if (msk) {
                if (key     > qg0)     s[ni][0] = -1e30f;
                if (key + 1 > qg0)     s[ni][1] = -1e30f;
                if (key     > qg0 + 8) s[ni][2] = -1e30f;
                if (key + 1 > qg0 + 8) s[ni][3] = -1e30f;
            }
        }

        // ---- online softmax
        float mx0 = -INFINITY, mx1 = -INFINITY;
#pragma unroll
        for (int ni = 0; ni < 8; ++ni) {
            mx0 = fmaxf(mx0, fmaxf(s[ni][0], s[ni][1]));
            mx1 = fmaxf(mx1, fmaxf(s[ni][2], s[ni][3]));
        }
        mx0 = fmaxf(mx0, __shfl_xor_sync(0xffffffffu, mx0, 1));
        mx0 = fmaxf(mx0, __shfl_xor_sync(0xffffffffu, mx0, 2));
        mx1 = fmaxf(mx1, __shfl_xor_sync(0xffffffffu, mx1, 1));
        mx1 = fmaxf(mx1, __shfl_xor_sync(0xffffffffu, mx1, 2));
        float m0n = fmaxf(m0, mx0), m1n = fmaxf(m1, mx1);
        float c0 = __expf(m0 - m0n), c1 = __expf(m1 - m1n);
        float ps0 = 0.f, ps1 = 0.f;
#pragma unroll
        for (int ni = 0; ni < 8; ++ni) {
            s[ni][0] = __expf(s[ni][0] - m0n);
            s[ni][1] = __expf(s[ni][1] - m0n);
            s[ni][2] = __expf(s[ni][2] - m1n);
            s[ni][3] = __expf(s[ni][3] - m1n);
            ps0 += s[ni][0] + s[ni][1];
            ps1 += s[ni][2] + s[ni][3];
        }
        ps0 += __shfl_xor_sync(0xffffffffu, ps0, 1);
        ps0 += __shfl_xor_sync(0xffffffffu, ps0, 2);
        ps1 += __shfl_xor_sync(0xffffffffu, ps1, 1);
        ps1 += __shfl_xor_sync(0xffffffffu, ps1, 2);
        l0 = l0 * c0 + ps0;
        l1 = l1 * c1 + ps1;
        m0 = m0n; m1 = m1n;
#pragma unroll
        for (int nn = 0; nn < 16; ++nn) {
            o[nn][0] *= c0; o[nn][1] *= c0;
            o[nn][2] *= c1; o[nn][3] *= c1;
        }

        // ---- O += P V : P(fp16) x (Vhi + Vlo)
        const uint32_t vbase = st + (uint32_t)KBUF;
#pragma unroll
        for (int kk2 = 0; kk2 < 4; ++kk2) {
            uint32_t pah[4];
            pah[0] = pack_h2(s[2 * kk2][0],     s[2 * kk2][1]);
            pah[1] = pack_h2(s[2 * kk2][2],     s[2 * kk2][3]);
            pah[2] = pack_h2(s[2 * kk2 + 1][0], s[2 * kk2 + 1][1]);
            pah[3] = pack_h2(s[2 * kk2 + 1][2], s[2 * kk2 + 1][3]);
#pragma unroll
            for (int nn8 = 0; nn8 < 8; ++nn8) {
                uint32_t vh[4], vl[4];
                uint32_t va = vbase + (uint32_t)((kk2 * 16 + (lane & 15)) * KROWB
                            + nn8 * 32 + ((lane >> 4) & 1) * 16);
                ldsm_x4t(vh, va);
                ldsm_x4t(vl, va + KBUF);
                mma_fp16(o[2 * nn8],     pah, &vh[0]);
                mma_fp16(o[2 * nn8],     pah, &vl[0]);
                mma_fp16(o[2 * nn8 + 1], pah, &vh[2]);
                mma_fp16(o[2 * nn8 + 1], pah, &vl[2]);
            }
        }
        __syncthreads();
    }

    // ---- normalize, split to bf16 hi/lo, write ctx [B,S,H]
    const float inv0 = 1.f / l0;
    const float inv1 = 1.f / l1;
    const int b  = bh >> 5;
    const int nh = bh & 31;
    const int row0 = q0 + wq * 16 + (lane >> 2);
#pragma unroll
    for (int nn = 0; nn < 16; ++nn) {
        int hd = nn * 8 + 2 * (lane & 3);
        size_t o0 = ((size_t)(b * Sc + row0)) * Hc + nh * HDc + hd;
        size_t o1 = o0 + 8 * (size_t)Hc;
        uint32_t hbits, lbits;
        split2(o[nn][0] * inv0, o[nn][1] * inv0, hbits, lbits);
        *(uint32_t*)(g_Chi + o0) = hbits;
        *(uint32_t*)(g_Clo + o0) = lbits;
        split2(o[nn][2] * inv1, o[nn][3] * inv1, hbits, lbits);
        *(uint32_t*)(g_Chi + o1) = hbits;
        *(uint32_t*)(g_Clo + o1) = lbits;
    }
}

// ---------------------------------------------------------------------------
// Launch
// ---------------------------------------------------------------------------
extern "C" void kernel_launch(void* const* d_in, const int* in_sizes, int n_in,
                              void* d_out, int out_size)
{
    (void)in_sizes; (void)n_in; (void)out_size;
    const float* hidden   = (const float*)d_in[0];
    const float* residual = (const float*)d_in[1];
    const float* alibi    = (const float*)d_in[2];
    // d_in[3] = attention_mask (pure causal; applied analytically)
    const float* W_qkv    = (const float*)d_in[4];
    const float* b_qkv    = (const float*)d_in[5];
    const float* W_dense  = (const float*)d_in[6];
    const float* b_dense  = (const float*)d_in[7];
    float* out = (float*)d_out;

    __nv_bfloat16 *Ahi, *Alo, *Wqhi, *Wqlo, *Wdhi, *Wdlo, *Chi, *Clo;
    cudaGetSymbolAddress((void**)&Ahi,  g_Ahi);
    cudaGetSymbolAddress((void**)&Alo,  g_Alo);
    cudaGetSymbolAddress((void**)&Wqhi, g_Wqhi);
    cudaGetSymbolAddress((void**)&Wqlo, g_Wqlo);
    cudaGetSymbolAddress((void**)&Wdhi, g_Wdhi);
    cudaGetSymbolAddress((void**)&Wdlo, g_Wdlo);
    cudaGetSymbolAddress((void**)&Chi,  g_Chi);
    cudaGetSymbolAddress((void**)&Clo,  g_Clo);

    // 1) split fp32 operands into bf16 hi/lo
    split_bf16<<<(4096 * 4096) / 1024, 256>>>(hidden,  Ahi,  Alo,  4096 * 4096);
    split_bf16<<<(12288 * 4096) / 1024, 256>>>(W_qkv,  Wqhi, Wqlo, 12288 * 4096);
    split_bf16<<<(4096 * 4096) / 1024, 256>>>(W_dense, Wdhi, Wdlo, 4096 * 4096);

    // 2) QKV projection -> q/k/v fp16 (q pre-scaled, q/v split, k pure)
    cudaFuncSetAttribute(hmma_gemm, cudaFuncAttributeMaxDynamicSharedMemorySize,
                         GEMM_SMEM);
    hmma_gemm<<<dim3(32, 96), 256, GEMM_SMEM>>>(Ahi, Alo, Wqhi, Wqlo,
                                                b_qkv, nullptr, nullptr, 4096, 0);

    // 3) MMA flash attention (fp16 2-pass) -> ctx bf16 hi/lo
    cudaFuncSetAttribute(attn_mma, cudaFuncAttributeMaxDynamicSharedMemorySize,
                         ATTN_SMEM);
    attn_mma<<<dim3(16, 64), 256, ATTN_SMEM>>>(alibi);

    // 4) dense projection (+bias +residual) -> out
    hmma_gemm<<<dim3(32, 32), 256, GEMM_SMEM>>>(Chi, Clo, Wdhi, Wdlo,
                                                b_dense, residual, out, 4096, 1);
}

// round 7
// speedup vs baseline: 5.0884x; 1.3816x over previous
#include <cuda_runtime.h>
#include <cuda_bf16.h>
#include <cuda_fp16.h>
#include <math.h>
#include <stdint.h>

// ---------------------------------------------------------------------------
// Problem constants
// ---------------------------------------------------------------------------
#define Bc  2
#define Sc  2048
#define Hc  4096
#define NHc 32
#define HDc 128
#define INV_NORM 0.08838834764831845f

// ---------------------------------------------------------------------------
// Device scratch (__device__ globals: allocation-free rule)
// All fp16 now: A (hidden) split hi/lo, weights pure, ctx split hi/lo.
// ---------------------------------------------------------------------------
__device__ __align__(256) __half g_Ahi[(size_t)4096 * 4096];
__device__ __align__(256) __half g_Alo[(size_t)4096 * 4096];
__device__ __align__(256) __half g_Wq [(size_t)12288 * 4096];
__device__ __align__(256) __half g_Wd [(size_t)4096 * 4096];
__device__ __align__(256) __half g_Chi[(size_t)4096 * 4096];
__device__ __align__(256) __half g_Clo[(size_t)4096 * 4096];

// attention operands: q split (pre-scaled by INV_NORM), k pure, v split
__device__ __align__(256) __half g_qhi[(size_t)Bc * NHc * Sc * HDc];
__device__ __align__(256) __half g_qlo[(size_t)Bc * NHc * Sc * HDc];
__device__ __align__(256) __half g_khi[(size_t)Bc * NHc * Sc * HDc];
__device__ __align__(256) __half g_vhi[(size_t)Bc * NHc * Sc * HDc];
__device__ __align__(256) __half g_vlo[(size_t)Bc * NHc * Sc * HDc];

// ---------------------------------------------------------------------------
// PTX helpers (sm_80-era only; harness PTX target is plain sm_103)
// ---------------------------------------------------------------------------
__device__ __forceinline__ uint32_t smem_u32(const void* p) {
    uint32_t a;
    asm("{ .reg .u64 t; cvta.to.shared.u64 t, %1; cvt.u32.u64 %0, t; }"
        : "=r"(a) : "l"(p));
    return a;
}
__device__ __forceinline__ void cp16(uint32_t s, const void* g) {
    asm volatile("cp.async.cg.shared.global [%0], [%1], 16;" :: "r"(s), "l"(g));
}
#define CP_COMMIT() asm volatile("cp.async.commit_group;" ::: "memory")
#define CP_WAIT1()  asm volatile("cp.async.wait_group 1;" ::: "memory")
#define CP_WAIT0()  asm volatile("cp.async.wait_group 0;" ::: "memory")

__device__ __forceinline__ void ldsm_x4(uint32_t* r, uint32_t a) {
    asm volatile("ldmatrix.sync.aligned.m8n8.x4.shared.b16 {%0,%1,%2,%3}, [%4];"
        : "=r"(r[0]), "=r"(r[1]), "=r"(r[2]), "=r"(r[3]) : "r"(a));
}
__device__ __forceinline__ void ldsm_x4t(uint32_t* r, uint32_t a) {
    asm volatile("ldmatrix.sync.aligned.m8n8.x4.trans.shared.b16 {%0,%1,%2,%3}, [%4];"
        : "=r"(r[0]), "=r"(r[1]), "=r"(r[2]), "=r"(r[3]) : "r"(a));
}
__device__ __forceinline__ void ldsm_x2(uint32_t* r, uint32_t a) {
    asm volatile("ldmatrix.sync.aligned.m8n8.x2.shared.b16 {%0,%1}, [%2];"
        : "=r"(r[0]), "=r"(r[1]) : "r"(a));
}
__device__ __forceinline__ void mma_fp16(float* c, const uint32_t* a, const uint32_t* b) {
    asm volatile(
        "mma.sync.aligned.m16n8k16.row.col.f32.f16.f16.f32 "
        "{%0,%1,%2,%3}, {%4,%5,%6,%7}, {%8,%9}, {%0,%1,%2,%3};"
        : "+f"(c[0]), "+f"(c[1]), "+f"(c[2]), "+f"(c[3])
        : "r"(a[0]), "r"(a[1]), "r"(a[2]), "r"(a[3]), "r"(b[0]), "r"(b[1]));
}
// fp16 hi/lo split of two fp32 (packed)
__device__ __forceinline__ void split2h(float x0, float x1, uint32_t& hi, uint32_t& lo) {
    __half2 h = __floats2half2_rn(x0, x1);
    __half2 l = __floats2half2_rn(x0 - __low2float(h), x1 - __high2float(h));
    hi = *(uint32_t*)&h;
    lo = *(uint32_t*)&l;
}
__device__ __forceinline__ uint32_t pack_h2(float x0, float x1) {
    __half2 h = __floats2half2_rn(x0, x1);
    return *(uint32_t*)&h;
}

// ---------------------------------------------------------------------------
// Kernel: split fp32 -> (hi, lo) fp16 pair
// ---------------------------------------------------------------------------
__global__ __launch_bounds__(256) void split_fp16(
    const float* __restrict__ x, __half* __restrict__ hi, __half* __restrict__ lo, int n)
{
    int i = (blockIdx.x * 256 + threadIdx.x) * 4;
    if (i >= n) return;
    float4 v = *(const float4*)(x + i);
    uint32_t h0, l0, h1, l1;
    split2h(v.x, v.y, h0, l0);
    split2h(v.z, v.w, h1, l1);
    uint32_t* hp = (uint32_t*)(hi + i);
    uint32_t* lp = (uint32_t*)(lo + i);
    hp[0] = h0; hp[1] = h1;
    lp[0] = l0; lp[1] = l1;
}

// ---------------------------------------------------------------------------
// Kernel: round fp32 -> fp16 (weights)
// ---------------------------------------------------------------------------
__global__ __launch_bounds__(256) void round_fp16(
    const float* __restrict__ x, __half* __restrict__ y, int n)
{
    int i = (blockIdx.x * 256 + threadIdx.x) * 4;
    if (i >= n) return;
    float4 v = *(const float4*)(x + i);
    uint32_t* yp = (uint32_t*)(y + i);
    yp[0] = pack_h2(v.x, v.y);
    yp[1] = pack_h2(v.z, v.w);
}

// ---------------------------------------------------------------------------
// Kernel: HMMA fp16 2-pass split GEMM.
//   C[128x128] = (Ahi + Alo)[M,K] * W[N,K]^T, fp32 accum.
//   Compact XOR-swizzled smem, 3-stage cp.async, one sync/iter, 2 CTAs/SM.
//   mode 0: QKV epilogue -> q (fp16 hi/lo, scaled), k (fp16), v (fp16 hi/lo)
//   mode 1: dense epilogue (+bias +residual -> out fp32)
// ---------------------------------------------------------------------------
#define BK        32
#define GBUF      8192              // 128 rows x 64B
#define STG_BYTES (3 * GBUF)        // Ahi, Alo, W = 24KB
#define GEMM_SMEM (3 * STG_BYTES)   // 73728

// swizzled address: row r (64B apart), 16B-chunk c in 0..3
__device__ __forceinline__ uint32_t swz(uint32_t base, int r, int c) {
    return base + (uint32_t)(r * 64 + ((c ^ ((r >> 1) & 3)) << 4));
}

__global__ __launch_bounds__(256, 2) void hmma_gemm(
    const __half* __restrict__ Ahi, const __half* __restrict__ Alo,
    const __half* __restrict__ W,
    const float* __restrict__ bias, const float* __restrict__ residual,
    float* __restrict__ out, int K, int mode)
{
    extern __shared__ char smem[];
    const uint32_t sb = smem_u32(smem);
    const int t    = threadIdx.x;
    const int wid  = t >> 5;
    const int lane = t & 31;
    const int wm   = wid >> 2;
    const int wn   = wid & 3;
    const int bm   = blockIdx.x * 128;
    const int bn   = blockIdx.y * 128;
    const int NK   = K / BK;

    float c[4][4][4];
#pragma unroll
    for (int mi = 0; mi < 4; mi++)
#pragma unroll
        for (int ni = 0; ni < 4; ni++)
#pragma unroll
            for (int e = 0; e < 4; e++) c[mi][ni][e] = 0.f;

    const __half* srcs[3] = { Ahi + (size_t)bm * K, Alo + (size_t)bm * K,
                              W   + (size_t)bn * K };

    auto load_stage = [&](int st, int k0) {
        uint32_t s0 = sb + (uint32_t)st * STG_BYTES;
#pragma unroll
        for (int bfi = 0; bfi < 3; bfi++) {
#pragma unroll
            for (int u = 0; u < 2; u++) {
                int id = u * 256 + t;
                int r  = id >> 2, cc = id & 3;
                cp16(swz(s0 + (uint32_t)bfi * GBUF, r, cc),
                     srcs[bfi] + (size_t)r * K + k0 + cc * 8);
            }
        }
        CP_COMMIT();
    };

    load_stage(0, 0);
    load_stage(1, BK);

    const int ra  = (lane & 15);
    const int ca0 = (lane >> 4);
    const int rb  = (lane & 7);
    const int cb0 = ((lane >> 3) & 1);

    int st = 0;
    for (int i = 0; i < NK; ++i) {
        if (i == NK - 1) CP_WAIT0(); else CP_WAIT1();
        __syncthreads();
        if (i + 2 < NK) {
            int st2 = st + 2;
            if (st2 >= 3) st2 -= 3;
            load_stage(st2, (i + 2) * BK);
        }

        const uint32_t sbase = sb + (uint32_t)st * STG_BYTES;
#pragma unroll
        for (int kb = 0; kb < 2; ++kb) {
            uint32_t bh[4][2];
#pragma unroll
            for (int ni = 0; ni < 4; ++ni) {
                uint32_t addr = swz(sbase + 2u * GBUF, wn * 32 + ni * 8 + rb, kb * 2 + cb0);
                ldsm_x2(bh[ni], addr);
            }
#pragma unroll
            for (int mi = 0; mi < 4; ++mi) {
                uint32_t ah[4], al[4];
                uint32_t addr = swz(sbase, wm * 64 + mi * 16 + ra, kb * 2 + ca0);
                ldsm_x4(ah, addr);
                ldsm_x4(al, addr + GBUF);
#pragma unroll
                for (int ni = 0; ni < 4; ++ni) {
                    mma_fp16(c[mi][ni], ah, bh[ni]);
                    mma_fp16(c[mi][ni], al, bh[ni]);
                }
            }
        }
        st = (st + 1 == 3) ? 0 : st + 1;
    }

    // ---- epilogue ----
    const int qr = lane >> 2;
    const int qc = (lane & 3) * 2;

    if (mode == 0) {
        const int nh    = bn / 384;
        const int which = (bn % 384) >> 7;
        const float scale = (which == 0) ? INV_NORM : 1.0f;
        __half *dhi = (which == 0) ? g_qhi : g_vhi;
        __half *dlo = (which == 0) ? g_qlo : g_vlo;
#pragma unroll
        for (int mi = 0; mi < 4; ++mi) {
#pragma unroll
            for (int rr = 0; rr < 2; ++rr) {
                int m = bm + wm * 64 + mi * 16 + qr + rr * 8;
                int b = m >> 11, ss = m & 2047;
                size_t rowoff = (((size_t)b * NHc + nh) * Sc + ss) * HDc;
#pragma unroll
                for (int ni = 0; ni < 4; ++ni) {
                    int hd = wn * 32 + ni * 8 + qc;
                    float x0 = (c[mi][ni][rr * 2 + 0] + __ldg(&bias[bn + hd]))     * scale;
                    float x1 = (c[mi][ni][rr * 2 + 1] + __ldg(&bias[bn + hd + 1])) * scale;
                    if (which == 1) {
                        *(uint32_t*)(g_khi + rowoff + hd) = pack_h2(x0, x1);
                    } else {
                        uint32_t hb, lb;
                        split2h(x0, x1, hb, lb);
                        *(uint32_t*)(dhi + rowoff + hd) = hb;
                        *(uint32_t*)(dlo + rowoff + hd) = lb;
                    }
                }
            }
        }
    } else {
#pragma unroll
        for (int mi = 0; mi < 4; ++mi) {
#pragma unroll
            for (int rr = 0; rr < 2; ++rr) {
                int m = bm + wm * 64 + mi * 16 + qr + rr * 8;
#pragma unroll
                for (int ni = 0; ni < 4; ++ni) {
                    int n = bn + wn * 32 + ni * 8 + qc;
                    size_t o = (size_t)m * Hc + n;
                    float2 rv = *(const float2*)(residual + o);
                    float2 v;
                    v.x = c[mi][ni][rr * 2 + 0] + __ldg(&bias[n])     + rv.x;
                    v.y = c[mi][ni][rr * 2 + 1] + __ldg(&bias[n + 1]) + rv.y;
                    *(float2*)(out + o) = v;
                }
            }
        }
    }
}

// ---------------------------------------------------------------------------
// Kernel: MMA flash attention, fp16 2-pass (Q split x K pure; P pure x V split)
//   grid = (16, 64); CTA: 8 warps, q-tile 128; k-tiles 64, double-buffered.
//   Writes ctx as fp16 hi/lo (g_Chi/g_Clo) for the 2-pass dense GEMM.
// ---------------------------------------------------------------------------
#define KROWB 272
#define KBUF  (64 * KROWB)           // 17408
#define KSTG  (3 * KBUF)             // khi, vhi, vlo = 52224
#define QBUF  (128 * KROWB)          // 34816
#define ATTN_SMEM (2 * QBUF + 2 * KSTG)  // 174080

__global__ __launch_bounds__(256, 1) void attn_mma(const float* __restrict__ alibi)
{
    extern __shared__ char smem[];
    const uint32_t sb   = smem_u32(smem);
    const uint32_t qsm  = sb;
    const uint32_t kvsm = sb + 2 * QBUF;

    const int t    = threadIdx.x;
    const int wq   = t >> 5;
    const int lane = t & 31;
    const int qt   = 15 - blockIdx.x;          // heavy tiles first
    const int bh   = blockIdx.y;
    const int q0   = qt * 128;

    // ---- Q tile load (hi, lo)
    {
        const __half* qh = g_qhi + ((size_t)bh * Sc + q0) * HDc;
        const __half* ql = g_qlo + ((size_t)bh * Sc + q0) * HDc;
#pragma unroll
        for (int u = 0; u < 8; ++u) {
            int id = u * 256 + t;
            int r = id >> 4, cc = id & 15;
            cp16(qsm + (uint32_t)(r * KROWB + cc * 16), qh + (size_t)r * 128 + cc * 8);
            cp16(qsm + QBUF + (uint32_t)(r * KROWB + cc * 16), ql + (size_t)r * 128 + cc * 8);
        }
        CP_COMMIT();
    }

    auto load_kv = [&](int st, int kt) {
        uint32_t d0 = kvsm + (uint32_t)st * KSTG;
        size_t goff = ((size_t)bh * Sc + (size_t)kt * 64) * HDc;
        const __half* srcs[3] = { g_khi + goff, g_vhi + goff, g_vlo + goff };
#pragma unroll
        for (int buf = 0; buf < 3; ++buf) {
#pragma unroll
            for (int u = 0; u < 4; ++u) {
                int id = u * 256 + t;
                int r = id >> 4, cc = id & 15;
                cp16(d0 + (uint32_t)buf * KBUF + (uint32_t)(r * KROWB + cc * 16),
                     srcs[buf] + (size_t)r * 128 + cc * 8);
            }
        }
        CP_COMMIT();
    };

    load_kv(0, 0);

    float o[16][4];
#pragma unroll
    for (int nn = 0; nn < 16; ++nn)
#pragma unroll
        for (int e = 0; e < 4; ++e) o[nn][e] = 0.f;
    float m0 = -INFINITY, m1 = -INFINITY, l0 = 0.f, l1 = 0.f;

    const float* al = alibi + (size_t)bh * Sc;
    const int qg0 = q0 + wq * 16 + (lane >> 2);
    const int ktmax = 2 * qt + 1;

    for (int kt = 0; kt <= ktmax; ++kt) {
        if (kt < ktmax) { load_kv((kt + 1) & 1, kt + 1); CP_WAIT1(); }
        else            { CP_WAIT0(); }
        __syncthreads();

        const uint32_t st = kvsm + (uint32_t)(kt & 1) * KSTG;

        // ---- S = Q K^T : Qhi*K + Qlo*K (fp16 2-pass)
        float s[8][4];
#pragma unroll
        for (int ni = 0; ni < 8; ++ni)
#pragma unroll
            for (int e = 0; e < 4; ++e) s[ni][e] = 0.f;

#pragma unroll
        for (int kk = 0; kk < 8; ++kk) {
            uint32_t qh[4], ql[4];
            uint32_t qa = qsm + (uint32_t)((wq * 16 + (lane & 15)) * KROWB
                        + kk * 32 + ((lane >> 4) & 1) * 16);
            ldsm_x4(qh, qa);
            ldsm_x4(ql, qa + QBUF);
#pragma unroll
            for (int nip = 0; nip < 4; ++nip) {
                uint32_t kh[4];
                uint32_t ka = st + (uint32_t)((nip * 16 + ((lane >> 4) & 1) * 8 + (lane & 7)) * KROWB
                            + kk * 32 + ((lane >> 3) & 1) * 16);
                ldsm_x4(kh, ka);
                mma_fp16(s[2 * nip],     qh, &kh[0]);
                mma_fp16(s[2 * nip],     ql, &kh[0]);
                mma_fp16(s[2 * nip + 1], qh, &kh[2]);
                mma_fp16(s[2 * nip + 1], ql, &kh[2]);
            }
        }

        // ---- alibi + causal mask
        const int ktb = kt * 64;
        const bool msk = (kt >= 2 * qt);
#pragma unroll
        for (int ni = 0; ni < 8; ++ni) {
            int key = ktb + ni * 8 + 2 * (lane & 3);
            float a0 = __ldg(al + key);
            float a1 = __ldg(al + key + 1);
            s[ni][0] += a0; s[ni][1] += a1;
            s[ni][2] += a0; s[ni][3] += a1;
            if (msk) {
                if (key     > qg0)     s[ni][0] = -1e30f;
                if (key + 1 > qg0)     s[ni][1] = -1e30f;
                if (key     > qg0 + 8) s[ni][2] = -1e30f;
                if (key + 1 > qg0 + 8) s[ni][3] = -1e30f;
            }
        }

        // ---- online softmax
        float mx0 = -INFINITY, mx1 = -INFINITY;
#pragma unroll
        for (int ni = 0; ni < 8; ++ni) {
            mx0 = fmaxf(mx0, fmaxf(s[ni][0], s[ni][1]));
            mx1 = fmaxf(mx1, fmaxf(s[ni][2], s[ni][3]));
        }
        mx0 = fmaxf(mx0, __shfl_xor_sync(0xffffffffu, mx0, 1));
        mx0 = fmaxf(mx0, __shfl_xor_sync(0xffffffffu, mx0, 2));
        mx1 = fmaxf(mx1, __shfl_xor_sync(0xffffffffu, mx1, 1));
        mx1 = fmaxf(mx1, __shfl_xor_sync(0xffffffffu, mx1, 2));
        float m0n = fmaxf(m0, mx0), m1n = fmaxf(m1, mx1);
        float c0 = __expf(m0 - m0n), c1 = __expf(m1 - m1n);
        float ps0 = 0.f, ps1 = 0.f;
#pragma unroll
        for (int ni = 0; ni < 8; ++ni) {
            s[ni][0] = __expf(s[ni][0] - m0n);
            s[ni][1] = __expf(s[ni][1] - m0n);
            s[ni][2] = __expf(s[ni][2] - m1n);
            s[ni][3] = __expf(s[ni][3] - m1n);
            ps0 += s[ni][0] + s[ni][1];
            ps1 += s[ni][2] + s[ni][3];
        }
        ps0 += __shfl_xor_sync(0xffffffffu, ps0, 1);
        ps0 += __shfl_xor_sync(0xffffffffu, ps0, 2);
        ps1 += __shfl_xor_sync(0xffffffffu, ps1, 1);
        ps1 += __shfl_xor_sync(0xffffffffu, ps1, 2);
        l0 = l0 * c0 + ps0;
        l1 = l1 * c1 + ps1;
        m0 = m0n; m1 = m1n;
#pragma unroll
        for (int nn = 0; nn < 16; ++nn) {
            o[nn][0] *= c0; o[nn][1] *= c0;
            o[nn][2] *= c1; o[nn][3] *= c1;
        }

        // ---- O += P V : P(fp16) x (Vhi + Vlo)
        const uint32_t vbase = st + (uint32_t)KBUF;
#pragma unroll
        for (int kk2 = 0; kk2 < 4; ++kk2) {
            uint32_t pah[4];
            pah[0] = pack_h2(s[2 * kk2][0],     s[2 * kk2][1]);
            pah[1] = pack_h2(s[2 * kk2][2],     s[2 * kk2][3]);
            pah[2] = pack_h2(s[2 * kk2 + 1][0], s[2 * kk2 + 1][1]);
            pah[3] = pack_h2(s[2 * kk2 + 1][2], s[2 * kk2 + 1][3]);
#pragma unroll
            for (int nn8 = 0; nn8 < 8; ++nn8) {
                uint32_t vh[4], vl[4];
                uint32_t va = vbase + (uint32_t)((kk2 * 16 + (lane & 15)) * KROWB
                            + nn8 * 32 + ((lane >> 4) & 1) * 16);
                ldsm_x4t(vh, va);
                ldsm_x4t(vl, va + KBUF);
                mma_fp16(o[2 * nn8],     pah, &vh[0]);
                mma_fp16(o[2 * nn8],     pah, &vl[0]);
                mma_fp16(o[2 * nn8 + 1], pah, &vh[2]);
                mma_fp16(o[2 * nn8 + 1], pah, &vl[2]);
            }
        }
        __syncthreads();
    }

    // ---- normalize, split to fp16 hi/lo, write ctx [B,S,H]
    const float inv0 = 1.f / l0;
    const float inv1 = 1.f / l1;
    const int b  = bh >> 5;
    const int nh = bh & 31;
    const int row0 = q0 + wq * 16 + (lane >> 2);
#pragma unroll
    for (int nn = 0; nn < 16; ++nn) {
        int hd = nn * 8 + 2 * (lane & 3);
        size_t o0 = ((size_t)(b * Sc + row0)) * Hc + nh * HDc + hd;
        size_t o1 = o0 + 8 * (size_t)Hc;
        uint32_t hbits, lbits;
        split2h(o[nn][0] * inv0, o[nn][1] * inv0, hbits, lbits);
        *(uint32_t*)(g_Chi + o0) = hbits;
        *(uint32_t*)(g_Clo + o0) = lbits;
        split2h(o[nn][2] * inv1, o[nn][3] * inv1, hbits, lbits);
        *(uint32_t*)(g_Chi + o1) = hbits;
        *(uint32_t*)(g_Clo + o1) = lbits;
    }
}

// ---------------------------------------------------------------------------
// Launch
// ---------------------------------------------------------------------------
extern "C" void kernel_launch(void* const* d_in, const int* in_sizes, int n_in,
                              void* d_out, int out_size)
{
    (void)in_sizes; (void)n_in; (void)out_size;
    const float* hidden   = (const float*)d_in[0];
    const float* residual = (const float*)d_in[1];
    const float* alibi    = (const float*)d_in[2];
    // d_in[3] = attention_mask (pure causal; applied analytically)
    const float* W_qkv    = (const float*)d_in[4];
    const float* b_qkv    = (const float*)d_in[5];
    const float* W_dense  = (const float*)d_in[6];
    const float* b_dense  = (const float*)d_in[7];
    float* out = (float*)d_out;

    __half *Ahi, *Alo, *Wq, *Wd, *Chi, *Clo;
    cudaGetSymbolAddress((void**)&Ahi, g_Ahi);
    cudaGetSymbolAddress((void**)&Alo, g_Alo);
    cudaGetSymbolAddress((void**)&Wq,  g_Wq);
    cudaGetSymbolAddress((void**)&Wd,  g_Wd);
    cudaGetSymbolAddress((void**)&Chi, g_Chi);
    cudaGetSymbolAddress((void**)&Clo, g_Clo);

    // 1) convert operands: hidden -> fp16 hi/lo, weights -> fp16
    split_fp16<<<(4096 * 4096) / 1024, 256>>>(hidden, Ahi, Alo, 4096 * 4096);
    round_fp16<<<(12288 * 4096) / 1024, 256>>>(W_qkv,  Wq, 12288 * 4096);
    round_fp16<<<(4096 * 4096) / 1024, 256>>>(W_dense, Wd, 4096 * 4096);

    // 2) QKV projection (fp16 2-pass) -> q/k/v fp16 (q pre-scaled, q/v split)
    cudaFuncSetAttribute(hmma_gemm, cudaFuncAttributeMaxDynamicSharedMemorySize,
                         GEMM_SMEM);
    hmma_gemm<<<dim3(32, 96), 256, GEMM_SMEM>>>(Ahi, Alo, Wq,
                                                b_qkv, nullptr, nullptr, 4096, 0);

    // 3) MMA flash attention (fp16 2-pass) -> ctx fp16 hi/lo
    cudaFuncSetAttribute(attn_mma, cudaFuncAttributeMaxDynamicSharedMemorySize,
                         ATTN_SMEM);
    attn_mma<<<dim3(16, 64), 256, ATTN_SMEM>>>(alibi);

    // 4) dense projection (fp16 2-pass, +bias +residual) -> out
    hmma_gemm<<<dim3(32, 32), 256, GEMM_SMEM>>>(Chi, Clo, Wd,
                                                b_dense, residual, out, 4096, 1);
}

// round 8
// speedup vs baseline: 7.9380x; 1.5600x over previous
#include <cuda_runtime.h>
#include <cuda_fp16.h>
#include <math.h>
#include <stdint.h>

// ---------------------------------------------------------------------------
// Problem constants
// ---------------------------------------------------------------------------
#define Bc  2
#define Sc  2048
#define Hc  4096
#define NHc 32
#define HDc 128
#define INV_NORM 0.08838834764831845f

// ---------------------------------------------------------------------------
// Device scratch (__device__ globals: allocation-free rule). All fp16.
// ---------------------------------------------------------------------------
__device__ __align__(256) __half g_A [(size_t)4096 * 4096];    // hidden, fp16
__device__ __align__(256) __half g_Wq[(size_t)12288 * 4096];
__device__ __align__(256) __half g_Wd[(size_t)4096 * 4096];
__device__ __align__(256) __half g_C [(size_t)4096 * 4096];    // ctx, fp16

// attention operands: q split (pre-scaled by INV_NORM), k pure, v split
__device__ __align__(256) __half g_qhi[(size_t)Bc * NHc * Sc * HDc];
__device__ __align__(256) __half g_qlo[(size_t)Bc * NHc * Sc * HDc];
__device__ __align__(256) __half g_khi[(size_t)Bc * NHc * Sc * HDc];
__device__ __align__(256) __half g_vhi[(size_t)Bc * NHc * Sc * HDc];
__device__ __align__(256) __half g_vlo[(size_t)Bc * NHc * Sc * HDc];

// ---------------------------------------------------------------------------
// PTX helpers (sm_80-era only; harness PTX target is plain sm_103)
// ---------------------------------------------------------------------------
__device__ __forceinline__ uint32_t smem_u32(const void* p) {
    uint32_t a;
    asm("{ .reg .u64 t; cvta.to.shared.u64 t, %1; cvt.u32.u64 %0, t; }"
        : "=r"(a) : "l"(p));
    return a;
}
__device__ __forceinline__ void cp16(uint32_t s, const void* g) {
    asm volatile("cp.async.cg.shared.global [%0], [%1], 16;" :: "r"(s), "l"(g));
}
#define CP_COMMIT() asm volatile("cp.async.commit_group;" ::: "memory")
#define CP_WAIT2()  asm volatile("cp.async.wait_group 2;" ::: "memory")
#define CP_WAIT1()  asm volatile("cp.async.wait_group 1;" ::: "memory")
#define CP_WAIT0()  asm volatile("cp.async.wait_group 0;" ::: "memory")

__device__ __forceinline__ void ldsm_x4(uint32_t* r, uint32_t a) {
    asm volatile("ldmatrix.sync.aligned.m8n8.x4.shared.b16 {%0,%1,%2,%3}, [%4];"
        : "=r"(r[0]), "=r"(r[1]), "=r"(r[2]), "=r"(r[3]) : "r"(a));
}
__device__ __forceinline__ void ldsm_x4t(uint32_t* r, uint32_t a) {
    asm volatile("ldmatrix.sync.aligned.m8n8.x4.trans.shared.b16 {%0,%1,%2,%3}, [%4];"
        : "=r"(r[0]), "=r"(r[1]), "=r"(r[2]), "=r"(r[3]) : "r"(a));
}
__device__ __forceinline__ void mma_fp16(float* c, const uint32_t* a, const uint32_t* b) {
    asm volatile(
        "mma.sync.aligned.m16n8k16.row.col.f32.f16.f16.f32 "
        "{%0,%1,%2,%3}, {%4,%5,%6,%7}, {%8,%9}, {%0,%1,%2,%3};"
        : "+f"(c[0]), "+f"(c[1]), "+f"(c[2]), "+f"(c[3])
        : "r"(a[0]), "r"(a[1]), "r"(a[2]), "r"(a[3]), "r"(b[0]), "r"(b[1]));
}
// fp16 hi/lo split of two fp32 (packed)
__device__ __forceinline__ void split2h(float x0, float x1, uint32_t& hi, uint32_t& lo) {
    __half2 h = __floats2half2_rn(x0, x1);
    __half2 l = __floats2half2_rn(x0 - __low2float(h), x1 - __high2float(h));
    hi = *(uint32_t*)&h;
    lo = *(uint32_t*)&l;
}
__device__ __forceinline__ uint32_t pack_h2(float x0, float x1) {
    __half2 h = __floats2half2_rn(x0, x1);
    return *(uint32_t*)&h;
}

// ---------------------------------------------------------------------------
// Kernel: round fp32 -> fp16
// ---------------------------------------------------------------------------
__global__ __launch_bounds__(256) void round_fp16(
    const float* __restrict__ x, __half* __restrict__ y, int n)
{
    int i = (blockIdx.x * 256 + threadIdx.x) * 4;
    if (i >= n) return;
    float4 v = *(const float4*)(x + i);
    uint32_t* yp = (uint32_t*)(y + i);
    yp[0] = pack_h2(v.x, v.y);
    yp[1] = pack_h2(v.z, v.w);
}

// ---------------------------------------------------------------------------
// Kernel: HMMA fp16 single-pass GEMM.
//   C[128x128] = A[M,K] * W[N,K]^T, fp32 accum.
//   Compact XOR-swizzled smem, 4-stage cp.async, one sync/iter, 2 CTAs/SM.
//   mode 0: QKV epilogue -> q (fp16 hi/lo, scaled), k (fp16), v (fp16 hi/lo)
//   mode 1: dense epilogue (+bias +residual -> out fp32)
// ---------------------------------------------------------------------------
#define BK        32
#define GBUF      8192              // 128 rows x 64B
#define STG_BYTES (2 * GBUF)        // A, W = 16KB
#define GEMM_SMEM (4 * STG_BYTES)   // 65536

// swizzled address: row r (64B apart), 16B-chunk c in 0..3
__device__ __forceinline__ uint32_t swz(uint32_t base, int r, int c) {
    return base + (uint32_t)(r * 64 + ((c ^ ((r >> 1) & 3)) << 4));
}

__global__ __launch_bounds__(256, 2) void hmma_gemm(
    const __half* __restrict__ A, const __half* __restrict__ W,
    const float* __restrict__ bias, const float* __restrict__ residual,
    float* __restrict__ out, int K, int mode)
{
    extern __shared__ char smem[];
    const uint32_t sb = smem_u32(smem);
    const int t    = threadIdx.x;
    const int wid  = t >> 5;
    const int lane = t & 31;
    const int wm   = wid >> 2;
    const int wn   = wid & 3;
    const int bm   = blockIdx.x * 128;
    const int bn   = blockIdx.y * 128;
    const int NK   = K / BK;

    float c[4][4][4];
#pragma unroll
    for (int mi = 0; mi < 4; mi++)
#pragma unroll
        for (int ni = 0; ni < 4; ni++)
#pragma unroll
            for (int e = 0; e < 4; e++) c[mi][ni][e] = 0.f;

    const __half* srcs[2] = { A + (size_t)bm * K, W + (size_t)bn * K };

    auto load_stage = [&](int st, int k0) {
        uint32_t s0 = sb + (uint32_t)st * STG_BYTES;
#pragma unroll
        for (int bfi = 0; bfi < 2; bfi++) {
#pragma unroll
            for (int u = 0; u < 2; u++) {
                int id = u * 256 + t;
                int r  = id >> 2, cc = id & 3;
                cp16(swz(s0 + (uint32_t)bfi * GBUF, r, cc),
                     srcs[bfi] + (size_t)r * K + k0 + cc * 8);
            }
        }
        CP_COMMIT();
    };

    load_stage(0, 0);
    load_stage(1, BK);
    load_stage(2, 2 * BK);

    // lane address components
    const int ra  = (lane & 15);                 // A: 16 rows
    const int ca0 = (lane >> 4);                 // A: k-half chunk
    const int rb  = ((lane >> 4) & 1) * 8 + (lane & 7);  // B x4: 16 rows (2 n-frags)
    const int cb0 = ((lane >> 3) & 1);           // B: k-half chunk

    for (int i = 0; i < NK; ++i) {
        if (i < NK - 2) CP_WAIT2(); else CP_WAIT0();
        __syncthreads();
        if (i + 3 < NK) load_stage((i + 3) & 3, (i + 3) * BK);

        const uint32_t sbase = sb + (uint32_t)(i & 3) * STG_BYTES;
#pragma unroll
        for (int kb = 0; kb < 2; ++kb) {
            uint32_t bfr[2][4];
#pragma unroll
            for (int pair = 0; pair < 2; ++pair) {
                uint32_t addr = swz(sbase + GBUF, wn * 32 + pair * 16 + rb, kb * 2 + cb0);
                ldsm_x4(bfr[pair], addr);
            }
#pragma unroll
            for (int mi = 0; mi < 4; ++mi) {
                uint32_t ah[4];
                uint32_t addr = swz(sbase, wm * 64 + mi * 16 + ra, kb * 2 + ca0);
                ldsm_x4(ah, addr);
                mma_fp16(c[mi][0], ah, &bfr[0][0]);
                mma_fp16(c[mi][1], ah, &bfr[0][2]);
                mma_fp16(c[mi][2], ah, &bfr[1][0]);
                mma_fp16(c[mi][3], ah, &bfr[1][2]);
            }
        }
    }

    // ---- epilogue ----
    const int qr = lane >> 2;
    const int qc = (lane & 3) * 2;

    if (mode == 0) {
        const int nh    = bn / 384;
        const int which = (bn % 384) >> 7;
        const float scale = (which == 0) ? INV_NORM : 1.0f;
        __half *dhi = (which == 0) ? g_qhi : g_vhi;
        __half *dlo = (which == 0) ? g_qlo : g_vlo;
#pragma unroll
        for (int mi = 0; mi < 4; ++mi) {
#pragma unroll
            for (int rr = 0; rr < 2; ++rr) {
                int m = bm + wm * 64 + mi * 16 + qr + rr * 8;
                int b = m >> 11, ss = m & 2047;
                size_t rowoff = (((size_t)b * NHc + nh) * Sc + ss) * HDc;
#pragma unroll
                for (int ni = 0; ni < 4; ++ni) {
                    int hd = wn * 32 + ni * 8 + qc;
                    float x0 = (c[mi][ni][rr * 2 + 0] + __ldg(&bias[bn + hd]))     * scale;
                    float x1 = (c[mi][ni][rr * 2 + 1] + __ldg(&bias[bn + hd + 1])) * scale;
                    if (which == 1) {
                        *(uint32_t*)(g_khi + rowoff + hd) = pack_h2(x0, x1);
                    } else {
                        uint32_t hb, lb;
                        split2h(x0, x1, hb, lb);
                        *(uint32_t*)(dhi + rowoff + hd) = hb;
                        *(uint32_t*)(dlo + rowoff + hd) = lb;
                    }
                }
            }
        }
    } else {
#pragma unroll
        for (int mi = 0; mi < 4; ++mi) {
#pragma unroll
            for (int rr = 0; rr < 2; ++rr) {
                int m = bm + wm * 64 + mi * 16 + qr + rr * 8;
#pragma unroll
                for (int ni = 0; ni < 4; ++ni) {
                    int n = bn + wn * 32 + ni * 8 + qc;
                    size_t o = (size_t)m * Hc + n;
                    float2 rv = *(const float2*)(residual + o);
                    float2 v;
                    v.x = c[mi][ni][rr * 2 + 0] + __ldg(&bias[n])     + rv.x;
                    v.y = c[mi][ni][rr * 2 + 1] + __ldg(&bias[n + 1]) + rv.y;
                    *(float2*)(out + o) = v;
                }
            }
        }
    }
}

// ---------------------------------------------------------------------------
// Kernel: MMA flash attention, fp16 2-pass (Q split x K pure; P pure x V split)
//   grid = (16, 64); CTA: 8 warps, q-tile 128; k-tiles 64, double-buffered.
//   Writes ctx as fp16 (g_C) in [B,S,H] for the single-pass dense GEMM.
// ---------------------------------------------------------------------------
#define KROWB 272
#define KBUF  (64 * KROWB)           // 17408
#define KSTG  (3 * KBUF)             // khi, vhi, vlo = 52224
#define QBUF  (128 * KROWB)          // 34816
#define ATTN_SMEM (2 * QBUF + 2 * KSTG)  // 174080

__global__ __launch_bounds__(256, 1) void attn_mma(const float* __restrict__ alibi)
{
    extern __shared__ char smem[];
    const uint32_t sb   = smem_u32(smem);
    const uint32_t qsm  = sb;
    const uint32_t kvsm = sb + 2 * QBUF;

    const int t    = threadIdx.x;
    const int wq   = t >> 5;
    const int lane = t & 31;
    const int qt   = 15 - blockIdx.x;          // heavy tiles first
    const int bh   = blockIdx.y;
    const int q0   = qt * 128;

    // ---- Q tile load (hi, lo)
    {
        const __half* qh = g_qhi + ((size_t)bh * Sc + q0) * HDc;
        const __half* ql = g_qlo + ((size_t)bh * Sc + q0) * HDc;
#pragma unroll
        for (int u = 0; u < 8; ++u) {
            int id = u * 256 + t;
            int r = id >> 4, cc = id & 15;
            cp16(qsm + (uint32_t)(r * KROWB + cc * 16), qh + (size_t)r * 128 + cc * 8);
            cp16(qsm + QBUF + (uint32_t)(r * KROWB + cc * 16), ql + (size_t)r * 128 + cc * 8);
        }
        CP_COMMIT();
    }

    auto load_kv = [&](int st, int kt) {
        uint32_t d0 = kvsm + (uint32_t)st * KSTG;
        size_t goff = ((size_t)bh * Sc + (size_t)kt * 64) * HDc;
        const __half* srcs[3] = { g_khi + goff, g_vhi + goff, g_vlo + goff };
#pragma unroll
        for (int buf = 0; buf < 3; ++buf) {
#pragma unroll
            for (int u = 0; u < 4; ++u) {
                int id = u * 256 + t;
                int r = id >> 4, cc = id & 15;
                cp16(d0 + (uint32_t)buf * KBUF + (uint32_t)(r * KROWB + cc * 16),
                     srcs[buf] + (size_t)r * 128 + cc * 8);
            }
        }
        CP_COMMIT();
    };

    load_kv(0, 0);

    float o[16][4];
#pragma unroll
    for (int nn = 0; nn < 16; ++nn)
#pragma unroll
        for (int e = 0; e < 4; ++e) o[nn][e] = 0.f;
    float m0 = -INFINITY, m1 = -INFINITY, l0 = 0.f, l1 = 0.f;

    const float* al = alibi + (size_t)bh * Sc;
    const int qg0 = q0 + wq * 16 + (lane >> 2);
    const int ktmax = 2 * qt + 1;

    for (int kt = 0; kt <= ktmax; ++kt) {
        if (kt < ktmax) { load_kv((kt + 1) & 1, kt + 1); CP_WAIT1(); }
        else            { CP_WAIT0(); }
        __syncthreads();

        const uint32_t st = kvsm + (uint32_t)(kt & 1) * KSTG;

        // ---- S = Q K^T : Qhi*K + Qlo*K (fp16 2-pass)
        float s[8][4];
#pragma unroll
        for (int ni = 0; ni < 8; ++ni)
#pragma unroll
            for (int e = 0; e < 4; ++e) s[ni][e] = 0.f;

#pragma unroll
        for (int kk = 0; kk < 8; ++kk) {
            uint32_t qh[4], ql[4];
            uint32_t qa = qsm + (uint32_t)((wq * 16 + (lane & 15)) * KROWB
                        + kk * 32 + ((lane >> 4) & 1) * 16);
            ldsm_x4(qh, qa);
            ldsm_x4(ql, qa + QBUF);
#pragma unroll
            for (int nip = 0; nip < 4; ++nip) {
                uint32_t kh[4];
                uint32_t ka = st + (uint32_t)((nip * 16 + ((lane >> 4) & 1) * 8 + (lane & 7)) * KROWB
                            + kk * 32 + ((lane >> 3) & 1) * 16);
                ldsm_x4(kh, ka);
                mma_fp16(s[2 * nip],     qh, &kh[0]);
                mma_fp16(s[2 * nip],     ql, &kh[0]);
                mma_fp16(s[2 * nip + 1], qh, &kh[2]);
                mma_fp16(s[2 * nip + 1], ql, &kh[2]);
            }
        }

        // ---- alibi + causal mask
        const int ktb = kt * 64;
        const bool msk = (kt >= 2 * qt);
#pragma unroll
        for (int ni = 0; ni < 8; ++ni) {
            int key = ktb + ni * 8 + 2 * (lane & 3);
            float a0 = __ldg(al + key);
            float a1 = __ldg(al + key + 1);
            s[ni][0] += a0; s[ni][1] += a1;
            s[ni][2] += a0; s[ni][3] += a1;
            if (msk) {
                if (key     > qg0)     s[ni][0] = -1e30f;
                if (key + 1 > qg0)     s[ni][1] = -1e30f;
                if (key     > qg0 + 8) s[ni][2] = -1e30f;
                if (key + 1 > qg0 + 8) s[ni][3] = -1e30f;
            }
        }

        // ---- online softmax
        float mx0 = -INFINITY, mx1 = -INFINITY;
#pragma unroll
        for (int ni = 0; ni < 8; ++ni) {
            mx0 = fmaxf(mx0, fmaxf(s[ni][0], s[ni][1]));
            mx1 = fmaxf(mx1, fmaxf(s[ni][2], s[ni][3]));
        }
        mx0 = fmaxf(mx0, __shfl_xor_sync(0xffffffffu, mx0, 1));
        mx0 = fmaxf(mx0, __shfl_xor_sync(0xffffffffu, mx0, 2));
        mx1 = fmaxf(mx1, __shfl_xor_sync(0xffffffffu, mx1, 1));
        mx1 = fmaxf(mx1, __shfl_xor_sync(0xffffffffu, mx1, 2));
        float m0n = fmaxf(m0, mx0), m1n = fmaxf(m1, mx1);
        float c0 = __expf(m0 - m0n), c1 = __expf(m1 - m1n);
        float ps0 = 0.f, ps1 = 0.f;
#pragma unroll
        for (int ni = 0; ni < 8; ++ni) {
            s[ni][0] = __expf(s[ni][0] - m0n);
            s[ni][1] = __expf(s[ni][1] - m0n);
            s[ni][2] = __expf(s[ni][2] - m1n);
            s[ni][3] = __expf(s[ni][3] - m1n);
            ps0 += s[ni][0] + s[ni][1];
            ps1 += s[ni][2] + s[ni][3];
        }
        ps0 += __shfl_xor_sync(0xffffffffu, ps0, 1);
        ps0 += __shfl_xor_sync(0xffffffffu, ps0, 2);
        ps1 += __shfl_xor_sync(0xffffffffu, ps1, 1);
        ps1 += __shfl_xor_sync(0xffffffffu, ps1, 2);
        l0 = l0 * c0 + ps0;
        l1 = l1 * c1 + ps1;
        m0 = m0n; m1 = m1n;
#pragma unroll
        for (int nn = 0; nn < 16; ++nn) {
            o[nn][0] *= c0; o[nn][1] *= c0;
            o[nn][2] *= c1; o[nn][3] *= c1;
        }

        // ---- O += P V : P(fp16) x (Vhi + Vlo)
        const uint32_t vbase = st + (uint32_t)KBUF;
#pragma unroll
        for (int kk2 = 0; kk2 < 4; ++kk2) {
            uint32_t pah[4];
            pah[0] = pack_h2(s[2 * kk2][0],     s[2 * kk2][1]);
            pah[1] = pack_h2(s[2 * kk2][2],     s[2 * kk2][3]);
            pah[2] = pack_h2(s[2 * kk2 + 1][0], s[2 * kk2 + 1][1]);
            pah[3] = pack_h2(s[2 * kk2 + 1][2], s[2 * kk2 + 1][3]);
#pragma unroll
            for (int nn8 = 0; nn8 < 8; ++nn8) {
                uint32_t vh[4], vl[4];
                uint32_t va = vbase + (uint32_t)((kk2 * 16 + (lane & 15)) * KROWB
                            + nn8 * 32 + ((lane >> 4) & 1) * 16);
                ldsm_x4t(vh, va);
                ldsm_x4t(vl, va + KBUF);
                mma_fp16(o[2 * nn8],     pah, &vh[0]);
                mma_fp16(o[2 * nn8],     pah, &vl[0]);
                mma_fp16(o[2 * nn8 + 1], pah, &vh[2]);
                mma_fp16(o[2 * nn8 + 1], pah, &vl[2]);
            }
        }
        __syncthreads();
    }

    // ---- normalize, round to fp16, write ctx [B,S,H]
    const float inv0 = 1.f / l0;
    const float inv1 = 1.f / l1;
    const int b  = bh >> 5;
    const int nh = bh & 31;
    const int row0 = q0 + wq * 16 + (lane >> 2);
#pragma unroll
    for (int nn = 0; nn < 16; ++nn) {
        int hd = nn * 8 + 2 * (lane & 3);
        size_t o0 = ((size_t)(b * Sc + row0)) * Hc + nh * HDc + hd;
        size_t o1 = o0 + 8 * (size_t)Hc;
        *(uint32_t*)(g_C + o0) = pack_h2(o[nn][0] * inv0, o[nn][1] * inv0);
        *(uint32_t*)(g_C + o1) = pack_h2(o[nn][2] * inv1, o[nn][3] * inv1);
    }
}

// ---------------------------------------------------------------------------
// Launch
// ---------------------------------------------------------------------------
extern "C" void kernel_launch(void* const* d_in, const int* in_sizes, int n_in,
                              void* d_out, int out_size)
{
    (void)in_sizes; (void)n_in; (void)out_size;
    const float* hidden   = (const float*)d_in[0];
    const float* residual = (const float*)d_in[1];
    const float* alibi    = (const float*)d_in[2];
    // d_in[3] = attention_mask (pure causal; applied analytically)
    const float* W_qkv    = (const float*)d_in[4];
    const float* b_qkv    = (const float*)d_in[5];
    const float* W_dense  = (const float*)d_in[6];
    const float* b_dense  = (const float*)d_in[7];
    float* out = (float*)d_out;

    __half *A, *Wq, *Wd, *C;
    cudaGetSymbolAddress((void**)&A,  g_A);
    cudaGetSymbolAddress((void**)&Wq, g_Wq);
    cudaGetSymbolAddress((void**)&Wd, g_Wd);
    cudaGetSymbolAddress((void**)&C,  g_C);

    // 1) convert operands to fp16
    round_fp16<<<(4096 * 4096) / 1024, 256>>>(hidden, A, 4096 * 4096);
    round_fp16<<<(12288 * 4096) / 1024, 256>>>(W_qkv,  Wq, 12288 * 4096);
    round_fp16<<<(4096 * 4096) / 1024, 256>>>(W_dense, Wd, 4096 * 4096);

    // 2) QKV projection (fp16 single-pass) -> q/k/v fp16 (q pre-scaled, q/v split)
    cudaFuncSetAttribute(hmma_gemm, cudaFuncAttributeMaxDynamicSharedMemorySize,
                         GEMM_SMEM);
    hmma_gemm<<<dim3(32, 96), 256, GEMM_SMEM>>>(A, Wq,
                                                b_qkv, nullptr, nullptr, 4096, 0);

    // 3) MMA flash attention (fp16 2-pass) -> ctx fp16
    cudaFuncSetAttribute(attn_mma, cudaFuncAttributeMaxDynamicSharedMemorySize,
                         ATTN_SMEM);
    attn_mma<<<dim3(16, 64), 256, ATTN_SMEM>>>(alibi);

    // 4) dense projection (fp16 single-pass, +bias +residual) -> out
    hmma_gemm<<<dim3(32, 32), 256, GEMM_SMEM>>>(C, Wd,
                                                b_dense, residual, out, 4096, 1);
}

// round 9
// speedup vs baseline: 8.7056x; 1.0967x over previous
#include <cuda_runtime.h>
#include <cuda_fp16.h>
#include <math.h>
#include <stdint.h>

// ---------------------------------------------------------------------------
// Problem constants
// ---------------------------------------------------------------------------
#define Bc  2
#define Sc  2048
#define Hc  4096
#define NHc 32
#define HDc 128
#define INV_NORM 0.08838834764831845f

// ---------------------------------------------------------------------------
// Device scratch (__device__ globals: allocation-free rule). All fp16.
// ---------------------------------------------------------------------------
__device__ __align__(256) __half g_A [(size_t)4096 * 4096];    // hidden, fp16
__device__ __align__(256) __half g_Wq[(size_t)12288 * 4096];
__device__ __align__(256) __half g_Wd[(size_t)4096 * 4096];
__device__ __align__(256) __half g_C [(size_t)4096 * 4096];    // ctx, fp16

// attention operands: q split (pre-scaled by INV_NORM), k pure, v split
__device__ __align__(256) __half g_qhi[(size_t)Bc * NHc * Sc * HDc];
__device__ __align__(256) __half g_qlo[(size_t)Bc * NHc * Sc * HDc];
__device__ __align__(256) __half g_khi[(size_t)Bc * NHc * Sc * HDc];
__device__ __align__(256) __half g_vhi[(size_t)Bc * NHc * Sc * HDc];
__device__ __align__(256) __half g_vlo[(size_t)Bc * NHc * Sc * HDc];

// ---------------------------------------------------------------------------
// PTX helpers (sm_80-era only; harness PTX target is plain sm_103)
// ---------------------------------------------------------------------------
__device__ __forceinline__ uint32_t smem_u32(const void* p) {
    uint32_t a;
    asm("{ .reg .u64 t; cvta.to.shared.u64 t, %1; cvt.u32.u64 %0, t; }"
        : "=r"(a) : "l"(p));
    return a;
}
__device__ __forceinline__ void cp16(uint32_t s, const void* g) {
    asm volatile("cp.async.cg.shared.global [%0], [%1], 16;" :: "r"(s), "l"(g));
}
#define CP_COMMIT() asm volatile("cp.async.commit_group;" ::: "memory")
#define CP_WAIT2()  asm volatile("cp.async.wait_group 2;" ::: "memory")
#define CP_WAIT1()  asm volatile("cp.async.wait_group 1;" ::: "memory")
#define CP_WAIT0()  asm volatile("cp.async.wait_group 0;" ::: "memory")

__device__ __forceinline__ void ldsm_x4(uint32_t* r, uint32_t a) {
    asm volatile("ldmatrix.sync.aligned.m8n8.x4.shared.b16 {%0,%1,%2,%3}, [%4];"
        : "=r"(r[0]), "=r"(r[1]), "=r"(r[2]), "=r"(r[3]) : "r"(a));
}
__device__ __forceinline__ void ldsm_x4t(uint32_t* r, uint32_t a) {
    asm volatile("ldmatrix.sync.aligned.m8n8.x4.trans.shared.b16 {%0,%1,%2,%3}, [%4];"
        : "=r"(r[0]), "=r"(r[1]), "=r"(r[2]), "=r"(r[3]) : "r"(a));
}
__device__ __forceinline__ void mma_fp16(float* c, const uint32_t* a, const uint32_t* b) {
    asm volatile(
        "mma.sync.aligned.m16n8k16.row.col.f32.f16.f16.f32 "
        "{%0,%1,%2,%3}, {%4,%5,%6,%7}, {%8,%9}, {%0,%1,%2,%3};"
        : "+f"(c[0]), "+f"(c[1]), "+f"(c[2]), "+f"(c[3])
        : "r"(a[0]), "r"(a[1]), "r"(a[2]), "r"(a[3]), "r"(b[0]), "r"(b[1]));
}
// fp16 hi/lo split of two fp32 (packed)
__device__ __forceinline__ void split2h(float x0, float x1, uint32_t& hi, uint32_t& lo) {
    __half2 h = __floats2half2_rn(x0, x1);
    __half2 l = __floats2half2_rn(x0 - __low2float(h), x1 - __high2float(h));
    hi = *(uint32_t*)&h;
    lo = *(uint32_t*)&l;
}
__device__ __forceinline__ uint32_t pack_h2(float x0, float x1) {
    __half2 h = __floats2half2_rn(x0, x1);
    return *(uint32_t*)&h;
}

// ---------------------------------------------------------------------------
// Kernel: round fp32 -> fp16
// ---------------------------------------------------------------------------
__global__ __launch_bounds__(256) void round_fp16(
    const float* __restrict__ x, __half* __restrict__ y, int n)
{
    int i = (blockIdx.x * 256 + threadIdx.x) * 4;
    if (i >= n) return;
    float4 v = *(const float4*)(x + i);
    uint32_t* yp = (uint32_t*)(y + i);
    yp[0] = pack_h2(v.x, v.y);
    yp[1] = pack_h2(v.z, v.w);
}

// ---------------------------------------------------------------------------
// Kernel: HMMA fp16 single-pass GEMM, 64x64 warp tiles.
//   CTA 128x128, 4 warps (2x2), warp tile 64x64, fp32 accum (128 regs/thread).
//   Compact XOR-swizzled smem, 4-stage cp.async, one sync/iter, 2 CTAs/SM.
//   mode 0: QKV epilogue -> q (fp16 hi/lo, scaled), k (fp16), v (fp16 hi/lo)
//   mode 1: dense epilogue (+bias +residual -> out fp32)
// ---------------------------------------------------------------------------
#define BK        32
#define GBUF      8192              // 128 rows x 64B
#define STG_BYTES (2 * GBUF)        // A, W = 16KB
#define GEMM_SMEM (4 * STG_BYTES)   // 65536

// swizzled address: row r (64B apart), 16B-chunk c in 0..3
__device__ __forceinline__ uint32_t swz(uint32_t base, int r, int c) {
    return base + (uint32_t)(r * 64 + ((c ^ ((r >> 1) & 3)) << 4));
}

__global__ __launch_bounds__(128, 2) void hmma_gemm(
    const __half* __restrict__ A, const __half* __restrict__ W,
    const float* __restrict__ bias, const float* __restrict__ residual,
    float* __restrict__ out, int K, int mode)
{
    extern __shared__ char smem[];
    const uint32_t sb = smem_u32(smem);
    const int t    = threadIdx.x;
    const int wid  = t >> 5;
    const int lane = t & 31;
    const int wm   = wid >> 1;       // 0..1 (64 rows each)
    const int wn   = wid & 1;        // 0..1 (64 cols each)
    const int bm   = blockIdx.x * 128;
    const int bn   = blockIdx.y * 128;
    const int NK   = K / BK;

    float c[4][8][4];
#pragma unroll
    for (int mi = 0; mi < 4; mi++)
#pragma unroll
        for (int ni = 0; ni < 8; ni++)
#pragma unroll
            for (int e = 0; e < 4; e++) c[mi][ni][e] = 0.f;

    const __half* srcs[2] = { A + (size_t)bm * K, W + (size_t)bn * K };

    auto load_stage = [&](int st, int k0) {
        uint32_t s0 = sb + (uint32_t)st * STG_BYTES;
#pragma unroll
        for (int bfi = 0; bfi < 2; bfi++) {
#pragma unroll
            for (int u = 0; u < 4; u++) {
                int id = u * 128 + t;          // 0..511
                int r  = id >> 2, cc = id & 3;
                cp16(swz(s0 + (uint32_t)bfi * GBUF, r, cc),
                     srcs[bfi] + (size_t)r * K + k0 + cc * 8);
            }
        }
        CP_COMMIT();
    };

    load_stage(0, 0);
    load_stage(1, BK);
    load_stage(2, 2 * BK);

    // lane address components
    const int ra  = (lane & 15);                          // A: 16 rows
    const int ca0 = (lane >> 4);                          // A: k-half chunk
    const int rb  = ((lane >> 4) & 1) * 8 + (lane & 7);   // B x4: 16 rows
    const int cb0 = ((lane >> 3) & 1);                    // B: k-half chunk

    for (int i = 0; i < NK; ++i) {
        if (i < NK - 2) CP_WAIT2(); else CP_WAIT0();
        __syncthreads();
        if (i + 3 < NK) load_stage((i + 3) & 3, (i + 3) * BK);

        const uint32_t sbase = sb + (uint32_t)(i & 3) * STG_BYTES;
#pragma unroll
        for (int kb = 0; kb < 2; ++kb) {
            uint32_t bfr[4][4];                 // 8 n-frags (2 per ldsm_x4)
#pragma unroll
            for (int pair = 0; pair < 4; ++pair) {
                uint32_t addr = swz(sbase + GBUF, wn * 64 + pair * 16 + rb, kb * 2 + cb0);
                ldsm_x4(bfr[pair], addr);
            }
#pragma unroll
            for (int mi = 0; mi < 4; ++mi) {
                uint32_t ah[4];
                uint32_t addr = swz(sbase, wm * 64 + mi * 16 + ra, kb * 2 + ca0);
                ldsm_x4(ah, addr);
#pragma unroll
                for (int pair = 0; pair < 4; ++pair) {
                    mma_fp16(c[mi][2 * pair],     ah, &bfr[pair][0]);
                    mma_fp16(c[mi][2 * pair + 1], ah, &bfr[pair][2]);
                }
            }
        }
    }

    // ---- epilogue ----
    const int qr = lane >> 2;
    const int qc = (lane & 3) * 2;

    if (mode == 0) {
        const int nh    = bn / 384;
        const int which = (bn % 384) >> 7;
        const float scale = (which == 0) ? INV_NORM : 1.0f;
        __half *dhi = (which == 0) ? g_qhi : g_vhi;
        __half *dlo = (which == 0) ? g_qlo : g_vlo;
#pragma unroll
        for (int mi = 0; mi < 4; ++mi) {
#pragma unroll
            for (int rr = 0; rr < 2; ++rr) {
                int m = bm + wm * 64 + mi * 16 + qr + rr * 8;
                int b = m >> 11, ss = m & 2047;
                size_t rowoff = (((size_t)b * NHc + nh) * Sc + ss) * HDc;
#pragma unroll
                for (int ni = 0; ni < 8; ++ni) {
                    int hd = wn * 64 + ni * 8 + qc;
                    float x0 = (c[mi][ni][rr * 2 + 0] + __ldg(&bias[bn + hd]))     * scale;
                    float x1 = (c[mi][ni][rr * 2 + 1] + __ldg(&bias[bn + hd + 1])) * scale;
                    if (which == 1) {
                        *(uint32_t*)(g_khi + rowoff + hd) = pack_h2(x0, x1);
                    } else {
                        uint32_t hb, lb;
                        split2h(x0, x1, hb, lb);
                        *(uint32_t*)(dhi + rowoff + hd) = hb;
                        *(uint32_t*)(dlo + rowoff + hd) = lb;
                    }
                }
            }
        }
    } else {
#pragma unroll
        for (int mi = 0; mi < 4; ++mi) {
#pragma unroll
            for (int rr = 0; rr < 2; ++rr) {
                int m = bm + wm * 64 + mi * 16 + qr + rr * 8;
#pragma unroll
                for (int ni = 0; ni < 8; ++ni) {
                    int n = bn + wn * 64 + ni * 8 + qc;
                    size_t o = (size_t)m * Hc + n;
                    float2 rv = *(const float2*)(residual + o);
                    float2 v;
                    v.x = c[mi][ni][rr * 2 + 0] + __ldg(&bias[n])     + rv.x;
                    v.y = c[mi][ni][rr * 2 + 1] + __ldg(&bias[n + 1]) + rv.y;
                    *(float2*)(out + o) = v;
                }
            }
        }
    }
}

// ---------------------------------------------------------------------------
// Kernel: MMA flash attention, fp16 2-pass (Q split x K pure; P pure x V split)
//   grid = (16, 64); CTA: 8 warps, q-tile 128; k-tiles 64, double-buffered.
//   Writes ctx as fp16 (g_C) in [B,S,H] for the single-pass dense GEMM.
// ---------------------------------------------------------------------------
#define KROWB 272
#define KBUF  (64 * KROWB)           // 17408
#define KSTG  (3 * KBUF)             // khi, vhi, vlo = 52224
#define QBUF  (128 * KROWB)          // 34816
#define ATTN_SMEM (2 * QBUF + 2 * KSTG)  // 174080

__global__ __launch_bounds__(256, 1) void attn_mma(const float* __restrict__ alibi)
{
    extern __shared__ char smem[];
    const uint32_t sb   = smem_u32(smem);
    const uint32_t qsm  = sb;
    const uint32_t kvsm = sb + 2 * QBUF;

    const int t    = threadIdx.x;
    const int wq   = t >> 5;
    const int lane = t & 31;
    const int qt   = 15 - blockIdx.x;          // heavy tiles first
    const int bh   = blockIdx.y;
    const int q0   = qt * 128;

    // ---- Q tile load (hi, lo)
    {
        const __half* qh = g_qhi + ((size_t)bh * Sc + q0) * HDc;
        const __half* ql = g_qlo + ((size_t)bh * Sc + q0) * HDc;
#pragma unroll
        for (int u = 0; u < 8; ++u) {
            int id = u * 256 + t;
            int r = id >> 4, cc = id & 15;
            cp16(qsm + (uint32_t)(r * KROWB + cc * 16), qh + (size_t)r * 128 + cc * 8);
            cp16(qsm + QBUF + (uint32_t)(r * KROWB + cc * 16), ql + (size_t)r * 128 + cc * 8);
        }
        CP_COMMIT();
    }

    auto load_kv = [&](int st, int kt) {
        uint32_t d0 = kvsm + (uint32_t)st * KSTG;
        size_t goff = ((size_t)bh * Sc + (size_t)kt * 64) * HDc;
        const __half* srcs[3] = { g_khi + goff, g_vhi + goff, g_vlo + goff };
#pragma unroll
        for (int buf = 0; buf < 3; ++buf) {
#pragma unroll
            for (int u = 0; u < 4; ++u) {
                int id = u * 256 + t;
                int r = id >> 4, cc = id & 15;
                cp16(d0 + (uint32_t)buf * KBUF + (uint32_t)(r * KROWB + cc * 16),
                     srcs[buf] + (size_t)r * 128 + cc * 8);
            }
        }
        CP_COMMIT();
    };

    load_kv(0, 0);

    float o[16][4];
#pragma unroll
    for (int nn = 0; nn < 16; ++nn)
#pragma unroll
        for (int e = 0; e < 4; ++e) o[nn][e] = 0.f;
    float m0 = -INFINITY, m1 = -INFINITY, l0 = 0.f, l1 = 0.f;

    const float* al = alibi + (size_t)bh * Sc;
    const int qg0 = q0 + wq * 16 + (lane >> 2);
    const int ktmax = 2 * qt + 1;

    for (int kt = 0; kt <= ktmax; ++kt) {
        if (kt < ktmax) { load_kv((kt + 1) & 1, kt + 1); CP_WAIT1(); }
        else            { CP_WAIT0(); }
        __syncthreads();

        const uint32_t st = kvsm + (uint32_t)(kt & 1) * KSTG;

        // ---- S = Q K^T : Qhi*K + Qlo*K (fp16 2-pass)
        float s[8][4];
#pragma unroll
        for (int ni = 0; ni < 8; ++ni)
#pragma unroll
            for (int e = 0; e < 4; ++e) s[ni][e] = 0.f;

#pragma unroll
        for (int kk = 0; kk < 8; ++kk) {
            uint32_t qh[4], ql[4];
            uint32_t qa = qsm + (uint32_t)((wq * 16 + (lane & 15)) * KROWB
                        + kk * 32 + ((lane >> 4) & 1) * 16);
            ldsm_x4(qh, qa);
            ldsm_x4(ql, qa + QBUF);
#pragma unroll
            for (int nip = 0; nip < 4; ++nip) {
                uint32_t kh[4];
                uint32_t ka = st + (uint32_t)((nip * 16 + ((lane >> 4) & 1) * 8 + (lane & 7)) * KROWB
                            + kk * 32 + ((lane >> 3) & 1) * 16);
                ldsm_x4(kh, ka);
                mma_fp16(s[2 * nip],     qh, &kh[0]);
                mma_fp16(s[2 * nip],     ql, &kh[0]);
                mma_fp16(s[2 * nip + 1], qh, &kh[2]);
                mma_fp16(s[2 * nip + 1], ql, &kh[2]);
            }
        }

        // ---- alibi + causal mask
        const int ktb = kt * 64;
        const bool msk = (kt >= 2 * qt);
#pragma unroll
        for (int ni = 0; ni < 8; ++ni) {
            int key = ktb + ni * 8 + 2 * (lane & 3);
            float a0 = __ldg(al + key);
            float a1 = __ldg(al + key + 1);
            s[ni][0] += a0; s[ni][1] += a1;
            s[ni][2] += a0; s[ni][3] += a1;
            if (msk) {
                if (key     > qg0)     s[ni][0] = -1e30f;
                if (key + 1 > qg0)     s[ni][1] = -1e30f;
                if (key     > qg0 + 8) s[ni][2] = -1e30f;
                if (key + 1 > qg0 + 8) s[ni][3] = -1e30f;
            }
        }

        // ---- online softmax
        float mx0 = -INFINITY, mx1 = -INFINITY;
#pragma unroll
        for (int ni = 0; ni < 8; ++ni) {
            mx0 = fmaxf(mx0, fmaxf(s[ni][0], s[ni][1]));
            mx1 = fmaxf(mx1, fmaxf(s[ni][2], s[ni][3]));
        }
        mx0 = fmaxf(mx0, __shfl_xor_sync(0xffffffffu, mx0, 1));
        mx0 = fmaxf(mx0, __shfl_xor_sync(0xffffffffu, mx0, 2));
        mx1 = fmaxf(mx1, __shfl_xor_sync(0xffffffffu, mx1, 1));
        mx1 = fmaxf(mx1, __shfl_xor_sync(0xffffffffu, mx1, 2));
        float m0n = fmaxf(m0, mx0), m1n = fmaxf(m1, mx1);
        float c0 = __expf(m0 - m0n), c1 = __expf(m1 - m1n);
        float ps0 = 0.f, ps1 = 0.f;
#pragma unroll
        for (int ni = 0; ni < 8; ++ni) {
            s[ni][0] = __expf(s[ni][0] - m0n);
            s[ni][1] = __expf(s[ni][1] - m0n);
            s[ni][2] = __expf(s[ni][2] - m1n);
            s[ni][3] = __expf(s[ni][3] - m1n);
            ps0 += s[ni][0] + s[ni][1];
            ps1 += s[ni][2] + s[ni][3];
        }
        ps0 += __shfl_xor_sync(0xffffffffu, ps0, 1);
        ps0 += __shfl_xor_sync(0xffffffffu, ps0, 2);
        ps1 += __shfl_xor_sync(0xffffffffu, ps1, 1);
        ps1 += __shfl_xor_sync(0xffffffffu, ps1, 2);
        l0 = l0 * c0 + ps0;
        l1 = l1 * c1 + ps1;
        m0 = m0n; m1 = m1n;
#pragma unroll
        for (int nn = 0; nn < 16; ++nn) {
            o[nn][0] *= c0; o[nn][1] *= c0;
            o[nn][2] *= c1; o[nn][3] *= c1;
        }

        // ---- O += P V : P(fp16) x (Vhi + Vlo)
        const uint32_t vbase = st + (uint32_t)KBUF;
#pragma unroll
        for (int kk2 = 0; kk2 < 4; ++kk2) {
            uint32_t pah[4];
            pah[0] = pack_h2(s[2 * kk2][0],     s[2 * kk2][1]);
            pah[1] = pack_h2(s[2 * kk2][2],     s[2 * kk2][3]);
            pah[2] = pack_h2(s[2 * kk2 + 1][0], s[2 * kk2 + 1][1]);
            pah[3] = pack_h2(s[2 * kk2 + 1][2], s[2 * kk2 + 1][3]);
#pragma unroll
            for (int nn8 = 0; nn8 < 8; ++nn8) {
                uint32_t vh[4], vl[4];
                uint32_t va = vbase + (uint32_t)((kk2 * 16 + (lane & 15)) * KROWB
                            + nn8 * 32 + ((lane >> 4) & 1) * 16);
                ldsm_x4t(vh, va);
                ldsm_x4t(vl, va + KBUF);
                mma_fp16(o[2 * nn8],     pah, &vh[0]);
                mma_fp16(o[2 * nn8],     pah, &vl[0]);
                mma_fp16(o[2 * nn8 + 1], pah, &vh[2]);
                mma_fp16(o[2 * nn8 + 1], pah, &vl[2]);
            }
        }
        __syncthreads();
    }

    // ---- normalize, round to fp16, write ctx [B,S,H]
    const float inv0 = 1.f / l0;
    const float inv1 = 1.f / l1;
    const int b  = bh >> 5;
    const int nh = bh & 31;
    const int row0 = q0 + wq * 16 + (lane >> 2);
#pragma unroll
    for (int nn = 0; nn < 16; ++nn) {
        int hd = nn * 8 + 2 * (lane & 3);
        size_t o0 = ((size_t)(b * Sc + row0)) * Hc + nh * HDc + hd;
        size_t o1 = o0 + 8 * (size_t)Hc;
        *(uint32_t*)(g_C + o0) = pack_h2(o[nn][0] * inv0, o[nn][1] * inv0);
        *(uint32_t*)(g_C + o1) = pack_h2(o[nn][2] * inv1, o[nn][3] * inv1);
    }
}

// ---------------------------------------------------------------------------
// Launch
// ---------------------------------------------------------------------------
extern "C" void kernel_launch(void* const* d_in, const int* in_sizes, int n_in,
                              void* d_out, int out_size)
{
    (void)in_sizes; (void)n_in; (void)out_size;
    const float* hidden   = (const float*)d_in[0];
    const float* residual = (const float*)d_in[1];
    const float* alibi    = (const float*)d_in[2];
    // d_in[3] = attention_mask (pure causal; applied analytically)
    const float* W_qkv    = (const float*)d_in[4];
    const float* b_qkv    = (const float*)d_in[5];
    const float* W_dense  = (const float*)d_in[6];
    const float* b_dense  = (const float*)d_in[7];
    float* out = (float*)d_out;

    __half *A, *Wq, *Wd, *C;
    cudaGetSymbolAddress((void**)&A,  g_A);
    cudaGetSymbolAddress((void**)&Wq, g_Wq);
    cudaGetSymbolAddress((void**)&Wd, g_Wd);
    cudaGetSymbolAddress((void**)&C,  g_C);

    // 1) convert operands to fp16
    round_fp16<<<(4096 * 4096) / 1024, 256>>>(hidden, A, 4096 * 4096);
    round_fp16<<<(12288 * 4096) / 1024, 256>>>(W_qkv,  Wq, 12288 * 4096);
    round_fp16<<<(4096 * 4096) / 1024, 256>>>(W_dense, Wd, 4096 * 4096);

    // 2) QKV projection (fp16 single-pass) -> q/k/v fp16 (q pre-scaled, q/v split)
    cudaFuncSetAttribute(hmma_gemm, cudaFuncAttributeMaxDynamicSharedMemorySize,
                         GEMM_SMEM);
    hmma_gemm<<<dim3(32, 96), 128, GEMM_SMEM>>>(A, Wq,
                                                b_qkv, nullptr, nullptr, 4096, 0);

    // 3) MMA flash attention (fp16 2-pass) -> ctx fp16
    cudaFuncSetAttribute(attn_mma, cudaFuncAttributeMaxDynamicSharedMemorySize,
                         ATTN_SMEM);
    attn_mma<<<dim3(16, 64), 256, ATTN_SMEM>>>(alibi);

    // 4) dense projection (fp16 single-pass, +bias +residual) -> out
    hmma_gemm<<<dim3(32, 32), 128, GEMM_SMEM>>>(C, Wd,
                                                b_dense, residual, out, 4096, 1);
}

// round 10
// speedup vs baseline: 9.7701x; 1.1223x over previous
#include <cuda_runtime.h>
#include <cuda_fp16.h>
#include <math.h>
#include <stdint.h>

// ---------------------------------------------------------------------------
// Problem constants
// ---------------------------------------------------------------------------
#define Bc  2
#define Sc  2048
#define Hc  4096
#define NHc 32
#define HDc 128
#define INV_NORM 0.08838834764831845f

// ---------------------------------------------------------------------------
// Device scratch (__device__ globals). All fp16, all single-copy now.
// ---------------------------------------------------------------------------
__device__ __align__(256) __half g_A [(size_t)4096 * 4096];    // hidden
__device__ __align__(256) __half g_Wq[(size_t)12288 * 4096];
__device__ __align__(256) __half g_Wd[(size_t)4096 * 4096];
__device__ __align__(256) __half g_C [(size_t)4096 * 4096];    // ctx [B,S,H]

// attention operands [B,NH,S,HD]: q pre-scaled by INV_NORM
__device__ __align__(256) __half g_q[(size_t)Bc * NHc * Sc * HDc];
__device__ __align__(256) __half g_k[(size_t)Bc * NHc * Sc * HDc];
__device__ __align__(256) __half g_v[(size_t)Bc * NHc * Sc * HDc];

// ---------------------------------------------------------------------------
// PTX helpers (sm_80-era only; harness PTX target is plain sm_103)
// ---------------------------------------------------------------------------
__device__ __forceinline__ uint32_t smem_u32(const void* p) {
    uint32_t a;
    asm("{ .reg .u64 t; cvta.to.shared.u64 t, %1; cvt.u32.u64 %0, t; }"
        : "=r"(a) : "l"(p));
    return a;
}
__device__ __forceinline__ void cp16(uint32_t s, const void* g) {
    asm volatile("cp.async.cg.shared.global [%0], [%1], 16;" :: "r"(s), "l"(g));
}
#define CP_COMMIT() asm volatile("cp.async.commit_group;" ::: "memory")
#define CP_WAIT1()  asm volatile("cp.async.wait_group 1;" ::: "memory")
#define CP_WAIT0()  asm volatile("cp.async.wait_group 0;" ::: "memory")

__device__ __forceinline__ void ldsm_x4(uint32_t* r, uint32_t a) {
    asm volatile("ldmatrix.sync.aligned.m8n8.x4.shared.b16 {%0,%1,%2,%3}, [%4];"
        : "=r"(r[0]), "=r"(r[1]), "=r"(r[2]), "=r"(r[3]) : "r"(a));
}
__device__ __forceinline__ void ldsm_x4t(uint32_t* r, uint32_t a) {
    asm volatile("ldmatrix.sync.aligned.m8n8.x4.trans.shared.b16 {%0,%1,%2,%3}, [%4];"
        : "=r"(r[0]), "=r"(r[1]), "=r"(r[2]), "=r"(r[3]) : "r"(a));
}
__device__ __forceinline__ void mma_fp16(float* c, const uint32_t* a, const uint32_t* b) {
    asm volatile(
        "mma.sync.aligned.m16n8k16.row.col.f32.f16.f16.f32 "
        "{%0,%1,%2,%3}, {%4,%5,%6,%7}, {%8,%9}, {%0,%1,%2,%3};"
        : "+f"(c[0]), "+f"(c[1]), "+f"(c[2]), "+f"(c[3])
        : "r"(a[0]), "r"(a[1]), "r"(a[2]), "r"(a[3]), "r"(b[0]), "r"(b[1]));
}
__device__ __forceinline__ uint32_t pack_h2(float x0, float x1) {
    __half2 h = __floats2half2_rn(x0, x1);
    return *(uint32_t*)&h;
}

// ---------------------------------------------------------------------------
// Kernel: round fp32 -> fp16
// ---------------------------------------------------------------------------
__global__ __launch_bounds__(256) void round_fp16(
    const float* __restrict__ x, __half* __restrict__ y, int n)
{
    int i = (blockIdx.x * 256 + threadIdx.x) * 4;
    if (i >= n) return;
    float4 v = *(const float4*)(x + i);
    uint32_t* yp = (uint32_t*)(y + i);
    yp[0] = pack_h2(v.x, v.y);
    yp[1] = pack_h2(v.z, v.w);
}

// ---------------------------------------------------------------------------
// Kernel: HMMA fp16 single-pass GEMM, 64x64 warp tiles, BK=64.
//   CTA 128x128, 4 warps (2x2), fp32 accum. 3-stage cp.async (32KB/stage),
//   one sync/iter, 2 CTAs/SM.
//   mode 0: QKV epilogue -> q (scaled) / k / v fp16 [B,NH,S,HD]
//   mode 1: dense epilogue (+bias +residual -> out fp32)
// ---------------------------------------------------------------------------
#define BK        64
#define GBUF      16384             // 128 rows x 128B
#define STG_BYTES (2 * GBUF)        // A, W = 32KB
#define GEMM_SMEM (3 * STG_BYTES)   // 98304

// 128B-row swizzle: row r, 16B-chunk c in 0..7
__device__ __forceinline__ uint32_t swz(uint32_t base, int r, int c) {
    return base + (uint32_t)(r * 128 + ((c ^ (r & 7)) << 4));
}

__global__ __launch_bounds__(128, 2) void hmma_gemm(
    const __half* __restrict__ A, const __half* __restrict__ W,
    const float* __restrict__ bias, const float* __restrict__ residual,
    float* __restrict__ out, int K, int mode)
{
    extern __shared__ char smem[];
    const uint32_t sb = smem_u32(smem);
    const int t    = threadIdx.x;
    const int wid  = t >> 5;
    const int lane = t & 31;
    const int wm   = wid >> 1;       // 0..1 (64 rows)
    const int wn   = wid & 1;        // 0..1 (64 cols)
    const int bm   = blockIdx.x * 128;
    const int bn   = blockIdx.y * 128;
    const int NK   = K / BK;         // 64

    float c[4][8][4];
#pragma unroll
    for (int mi = 0; mi < 4; mi++)
#pragma unroll
        for (int ni = 0; ni < 8; ni++)
#pragma unroll
            for (int e = 0; e < 4; e++) c[mi][ni][e] = 0.f;

    const __half* srcs[2] = { A + (size_t)bm * K, W + (size_t)bn * K };

    auto load_stage = [&](int st, int k0) {
        uint32_t s0 = sb + (uint32_t)st * STG_BYTES;
#pragma unroll
        for (int bfi = 0; bfi < 2; bfi++) {
#pragma unroll
            for (int u = 0; u < 8; u++) {
                int id = u * 128 + t;          // 0..1023
                int r  = id >> 3, cc = id & 7;
                cp16(swz(s0 + (uint32_t)bfi * GBUF, r, cc),
                     srcs[bfi] + (size_t)r * K + k0 + cc * 8);
            }
        }
        CP_COMMIT();
    };

    load_stage(0, 0);
    load_stage(1, BK);

    // lane address components
    const int ra  = (lane & 15);                          // A: 16 rows
    const int ca0 = (lane >> 4);                          // A: k-half chunk
    const int rb  = ((lane >> 4) & 1) * 8 + (lane & 7);   // B x4: 16 rows
    const int cb0 = ((lane >> 3) & 1);                    // B: k-half chunk

    for (int i = 0; i < NK; ++i) {
        if (i < NK - 1) CP_WAIT1(); else CP_WAIT0();
        __syncthreads();
        if (i + 2 < NK) {
            int s2 = i + 2;
            while (s2 >= 3) s2 -= 3;
            load_stage(s2, (i + 2) * BK);
        }

        int si = i; while (si >= 3) si -= 3;
        const uint32_t sbase = sb + (uint32_t)si * STG_BYTES;
#pragma unroll
        for (int kb = 0; kb < 4; ++kb) {                  // 4 x k16 per BK=64
            uint32_t bfr[4][4];
#pragma unroll
            for (int pair = 0; pair < 4; ++pair) {
                uint32_t addr = swz(sbase + GBUF, wn * 64 + pair * 16 + rb, kb * 2 + cb0);
                ldsm_x4(bfr[pair], addr);
            }
#pragma unroll
            for (int mi = 0; mi < 4; ++mi) {
                uint32_t ah[4];
                uint32_t addr = swz(sbase, wm * 64 + mi * 16 + ra, kb * 2 + ca0);
                ldsm_x4(ah, addr);
#pragma unroll
                for (int pair = 0; pair < 4; ++pair) {
                    mma_fp16(c[mi][2 * pair],     ah, &bfr[pair][0]);
                    mma_fp16(c[mi][2 * pair + 1], ah, &bfr[pair][2]);
                }
            }
        }
    }

    // ---- epilogue ----
    const int qr = lane >> 2;
    const int qc = (lane & 3) * 2;

    if (mode == 0) {
        const int nh    = bn / 384;
        const int which = (bn % 384) >> 7;
        const float scale = (which == 0) ? INV_NORM : 1.0f;
        __half* dst = (which == 0) ? g_q : ((which == 1) ? g_k : g_v);
#pragma unroll
        for (int mi = 0; mi < 4; ++mi) {
#pragma unroll
            for (int rr = 0; rr < 2; ++rr) {
                int m = bm + wm * 64 + mi * 16 + qr + rr * 8;
                int b = m >> 11, ss = m & 2047;
                size_t rowoff = (((size_t)b * NHc + nh) * Sc + ss) * HDc;
#pragma unroll
                for (int ni = 0; ni < 8; ++ni) {
                    int hd = wn * 64 + ni * 8 + qc;
                    float x0 = (c[mi][ni][rr * 2 + 0] + __ldg(&bias[bn + hd]))     * scale;
                    float x1 = (c[mi][ni][rr * 2 + 1] + __ldg(&bias[bn + hd + 1])) * scale;
                    *(uint32_t*)(dst + rowoff + hd) = pack_h2(x0, x1);
                }
            }
        }
    } else {
#pragma unroll
        for (int mi = 0; mi < 4; ++mi) {
#pragma unroll
            for (int rr = 0; rr < 2; ++rr) {
                int m = bm + wm * 64 + mi * 16 + qr + rr * 8;
#pragma unroll
                for (int ni = 0; ni < 8; ++ni) {
                    int n = bn + wn * 64 + ni * 8 + qc;
                    size_t o = (size_t)m * Hc + n;
                    float2 rv = *(const float2*)(residual + o);
                    float2 v;
                    v.x = c[mi][ni][rr * 2 + 0] + __ldg(&bias[n])     + rv.x;
                    v.y = c[mi][ni][rr * 2 + 1] + __ldg(&bias[n + 1]) + rv.y;
                    *(float2*)(out + o) = v;
                }
            }
        }
    }
}

// ---------------------------------------------------------------------------
// Kernel: MMA flash attention, pure fp16 (single-pass QK and PV).
//   grid = (16, 64); CTA: 8 warps, q-tile 128; k-tiles 64, 3-stage cp.async.
//   Writes ctx fp16 (g_C) in [B,S,H].
// ---------------------------------------------------------------------------
#define KROWB 272
#define KBUF  (64 * KROWB)           // 17408
#define KSTG  (2 * KBUF)             // k + v = 34816
#define QBUF  (128 * KROWB)          // 34816
#define ATTN_SMEM (QBUF + 3 * KSTG)  // 139264

__global__ __launch_bounds__(256, 1) void attn_mma(const float* __restrict__ alibi)
{
    extern __shared__ char smem[];
    const uint32_t sb   = smem_u32(smem);
    const uint32_t qsm  = sb;
    const uint32_t kvsm = sb + QBUF;

    const int t    = threadIdx.x;
    const int wq   = t >> 5;
    const int lane = t & 31;
    const int qt   = 15 - blockIdx.x;          // heavy tiles first
    const int bh   = blockIdx.y;
    const int q0   = qt * 128;

    auto load_kv = [&](int st, int kt) {
        uint32_t d0 = kvsm + (uint32_t)st * KSTG;
        size_t goff = ((size_t)bh * Sc + (size_t)kt * 64) * HDc;
        const __half* srcs[2] = { g_k + goff, g_v + goff };
#pragma unroll
        for (int buf = 0; buf < 2; ++buf) {
#pragma unroll
            for (int u = 0; u < 4; ++u) {
                int id = u * 256 + t;
                int r = id >> 4, cc = id & 15;
                cp16(d0 + (uint32_t)buf * KBUF + (uint32_t)(r * KROWB + cc * 16),
                     srcs[buf] + (size_t)r * 128 + cc * 8);
            }
        }
    };

    // group 0: Q tile + kv(0); group 1: kv(1)
    {
        const __half* qg = g_q + ((size_t)bh * Sc + q0) * HDc;
#pragma unroll
        for (int u = 0; u < 8; ++u) {
            int id = u * 256 + t;
            int r = id >> 4, cc = id & 15;
            cp16(qsm + (uint32_t)(r * KROWB + cc * 16), qg + (size_t)r * 128 + cc * 8);
        }
        load_kv(0, 0);
        CP_COMMIT();
    }
    const int ktmax = 2 * qt + 1;
    if (ktmax >= 1) { load_kv(1, 1); CP_COMMIT(); }

    float o[16][4];
#pragma unroll
    for (int nn = 0; nn < 16; ++nn)
#pragma unroll
        for (int e = 0; e < 4; ++e) o[nn][e] = 0.f;
    float m0 = -INFINITY, m1 = -INFINITY, l0 = 0.f, l1 = 0.f;

    const float* al = alibi + (size_t)bh * Sc;
    const int qg0 = q0 + wq * 16 + (lane >> 2);

    for (int kt = 0; kt <= ktmax; ++kt) {
        if (kt < ktmax) CP_WAIT1(); else CP_WAIT0();
        __syncthreads();
        if (kt + 2 <= ktmax) {
            int s2 = kt + 2; while (s2 >= 3) s2 -= 3;
            load_kv(s2, kt + 2);
            CP_COMMIT();
        }

        int si = kt; while (si >= 3) si -= 3;
        const uint32_t st = kvsm + (uint32_t)si * KSTG;

        // ---- S = Q K^T (pure fp16)
        float s[8][4];
#pragma unroll
        for (int ni = 0; ni < 8; ++ni)
#pragma unroll
            for (int e = 0; e < 4; ++e) s[ni][e] = 0.f;

#pragma unroll
        for (int kk = 0; kk < 8; ++kk) {
            uint32_t qh[4];
            uint32_t qa = qsm + (uint32_t)((wq * 16 + (lane & 15)) * KROWB
                        + kk * 32 + ((lane >> 4) & 1) * 16);
            ldsm_x4(qh, qa);
#pragma unroll
            for (int nip = 0; nip < 4; ++nip) {
                uint32_t kh[4];
                uint32_t ka = st + (uint32_t)((nip * 16 + ((lane >> 4) & 1) * 8 + (lane & 7)) * KROWB
                            + kk * 32 + ((lane >> 3) & 1) * 16);
                ldsm_x4(kh, ka);
                mma_fp16(s[2 * nip],     qh, &kh[0]);
                mma_fp16(s[2 * nip + 1], qh, &kh[2]);
            }
        }

        // ---- alibi + causal mask
        const int ktb = kt * 64;
        const bool msk = (kt >= 2 * qt);
#pragma unroll
        for (int ni = 0; ni < 8; ++ni) {
            int key = ktb + ni * 8 + 2 * (lane & 3);
            float a0 = __ldg(al + key);
            float a1 = __ldg(al + key + 1);
            s[ni][0] += a0; s[ni][1] += a1;
            s[ni][2] += a0; s[ni][3] += a1;
            if (msk) {
                if (key     > qg0)     s[ni][0] = -1e30f;
                if (key + 1 > qg0)     s[ni][1] = -1e30f;
                if (key     > qg0 + 8) s[ni][2] = -1e30f;
                if (key + 1 > qg0 + 8) s[ni][3] = -1e30f;
            }
        }

        // ---- online softmax
        float mx0 = -INFINITY, mx1 = -INFINITY;
#pragma unroll
        for (int ni = 0; ni < 8; ++ni) {
            mx0 = fmaxf(mx0, fmaxf(s[ni][0], s[ni][1]));
            mx1 = fmaxf(mx1, fmaxf(s[ni][2], s[ni][3]));
        }
        mx0 = fmaxf(mx0, __shfl_xor_sync(0xffffffffu, mx0, 1));
        mx0 = fmaxf(mx0, __shfl_xor_sync(0xffffffffu, mx0, 2));
        mx1 = fmaxf(mx1, __shfl_xor_sync(0xffffffffu, mx1, 1));
        mx1 = fmaxf(mx1, __shfl_xor_sync(0xffffffffu, mx1, 2));
        float m0n = fmaxf(m0, mx0), m1n = fmaxf(m1, mx1);
        float c0 = __expf(m0 - m0n), c1 = __expf(m1 - m1n);
        float ps0 = 0.f, ps1 = 0.f;
#pragma unroll
        for (int ni = 0; ni < 8; ++ni) {
            s[ni][0] = __expf(s[ni][0] - m0n);
            s[ni][1] = __expf(s[ni][1] - m0n);
            s[ni][2] = __expf(s[ni][2] - m1n);
            s[ni][3] = __expf(s[ni][3] - m1n);
            ps0 += s[ni][0] + s[ni][1];
            ps1 += s[ni][2] + s[ni][3];
        }
        ps0 += __shfl_xor_sync(0xffffffffu, ps0, 1);
        ps0 += __shfl_xor_sync(0xffffffffu, ps0, 2);
        ps1 += __shfl_xor_sync(0xffffffffu, ps1, 1);
        ps1 += __shfl_xor_sync(0xffffffffu, ps1, 2);
        l0 = l0 * c0 + ps0;
        l1 = l1 * c1 + ps1;
        m0 = m0n; m1 = m1n;
#pragma unroll
        for (int nn = 0; nn < 16; ++nn) {
            o[nn][0] *= c0; o[nn][1] *= c0;
            o[nn][2] *= c1; o[nn][3] *= c1;
        }

        // ---- O += P V (pure fp16)
        const uint32_t vbase = st + (uint32_t)KBUF;
#pragma unroll
        for (int kk2 = 0; kk2 < 4; ++kk2) {
            uint32_t pah[4];
            pah[0] = pack_h2(s[2 * kk2][0],     s[2 * kk2][1]);
            pah[1] = pack_h2(s[2 * kk2][2],     s[2 * kk2][3]);
            pah[2] = pack_h2(s[2 * kk2 + 1][0], s[2 * kk2 + 1][1]);
            pah[3] = pack_h2(s[2 * kk2 + 1][2], s[2 * kk2 + 1][3]);
#pragma unroll
            for (int nn8 = 0; nn8 < 8; ++nn8) {
                uint32_t vh[4];
                uint32_t va = vbase + (uint32_t)((kk2 * 16 + (lane & 15)) * KROWB
                            + nn8 * 32 + ((lane >> 4) & 1) * 16);
                ldsm_x4t(vh, va);
                mma_fp16(o[2 * nn8],     pah, &vh[0]);
                mma_fp16(o[2 * nn8 + 1], pah, &vh[2]);
            }
        }
        __syncthreads();
    }

    // ---- normalize, round to fp16, write ctx [B,S,H]
    const float inv0 = 1.f / l0;
    const float inv1 = 1.f / l1;
    const int b  = bh >> 5;
    const int nh = bh & 31;
    const int row0 = q0 + wq * 16 + (lane >> 2);
#pragma unroll
    for (int nn = 0; nn < 16; ++nn) {
        int hd = nn * 8 + 2 * (lane & 3);
        size_t o0 = ((size_t)(b * Sc + row0)) * Hc + nh * HDc + hd;
        size_t o1 = o0 + 8 * (size_t)Hc;
        *(uint32_t*)(g_C + o0) = pack_h2(o[nn][0] * inv0, o[nn][1] * inv0);
        *(uint32_t*)(g_C + o1) = pack_h2(o[nn][2] * inv1, o[nn][3] * inv1);
    }
}

// ---------------------------------------------------------------------------
// Launch
// ---------------------------------------------------------------------------
extern "C" void kernel_launch(void* const* d_in, const int* in_sizes, int n_in,
                              void* d_out, int out_size)
{
    (void)in_sizes; (void)n_in; (void)out_size;
    const float* hidden   = (const float*)d_in[0];
    const float* residual = (const float*)d_in[1];
    const float* alibi    = (const float*)d_in[2];
    // d_in[3] = attention_mask (pure causal; applied analytically)
    const float* W_qkv    = (const float*)d_in[4];
    const float* b_qkv    = (const float*)d_in[5];
    const float* W_dense  = (const float*)d_in[6];
    const float* b_dense  = (const float*)d_in[7];
    float* out = (float*)d_out;

    __half *A, *Wq, *Wd, *C;
    cudaGetSymbolAddress((void**)&A,  g_A);
    cudaGetSymbolAddress((void**)&Wq, g_Wq);
    cudaGetSymbolAddress((void**)&Wd, g_Wd);
    cudaGetSymbolAddress((void**)&C,  g_C);

    // 1) convert operands to fp16
    round_fp16<<<(4096 * 4096) / 1024, 256>>>(hidden, A, 4096 * 4096);
    round_fp16<<<(12288 * 4096) / 1024, 256>>>(W_qkv,  Wq, 12288 * 4096);
    round_fp16<<<(4096 * 4096) / 1024, 256>>>(W_dense, Wd, 4096 * 4096);

    // 2) QKV projection -> q (scaled) / k / v fp16
    cudaFuncSetAttribute(hmma_gemm, cudaFuncAttributeMaxDynamicSharedMemorySize,
                         GEMM_SMEM);
    hmma_gemm<<<dim3(32, 96), 128, GEMM_SMEM>>>(A, Wq,
                                                b_qkv, nullptr, nullptr, 4096, 0);

    // 3) MMA flash attention (pure fp16) -> ctx fp16
    cudaFuncSetAttribute(attn_mma, cudaFuncAttributeMaxDynamicSharedMemorySize,
                         ATTN_SMEM);
    attn_mma<<<dim3(16, 64), 256, ATTN_SMEM>>>(alibi);

    // 4) dense projection (+bias +residual) -> out
    hmma_gemm<<<dim3(32, 32), 128, GEMM_SMEM>>>(C, Wd,
                                                b_dense, residual, out, 4096, 1);
}